// round 5
// baseline (speedup 1.0000x reference)
#include <cuda_runtime.h>

// Problem constants
#define NTOT 32768      // total nodes (B*N)
#define BG   16         // graphs
#define NPG  2048       // nodes per graph
#define CIN  64
#define HID  128
#define KC   32
#define NE   524288     // edges
#define CAP  192        // per-node in-edge capacity (Poisson(16); 192 is astronomically safe)

#define SELU_SCALE 1.0507009873554805f
#define SELU_ALPHA 1.6732632423543772f
#define SQRT_K     5.656854249492380f   // sqrt(32)

// ---------------- device scratch (no runtime allocation allowed) ----------------
__device__ float g_s1[BG * CIN];
__device__ float g_s2[BG * CIN];
__device__ float g_na[BG * CIN];          // per-(graph,ch) affine a:  h = a*x + b
__device__ float g_nb[BG * CIN];
__device__ float g_hw[NTOT * HID];        // 16 MB  (normalized x) @ w1
__device__ float g_xd[NTOT * HID];        // 16 MB  post-GCN features
__device__ float g_sc[NTOT * KC];         // 4 MB   soft assignments s
__device__ int   g_cnt[NTOT];             // in-degree (excl self loop)
__device__ int   g_odeg[NTOT];            // out-degree (for DMoN degrees)
__device__ float g_dinv[NTOT];
__device__ float g_odegf[NTOT];
__device__ int   g_inlist[NTOT * CAP];    // 25 MB  CSR-ish slots: srcs per dst
__device__ float g_outacc[BG * KC * HID]; // s^T @ xd accumulators
__device__ float g_ssacc[BG * KC * KC];   // s^T @ s
__device__ float g_caacc[BG * KC];        // s^T @ degrees
__device__ float g_csacc[BG * KC];        // cluster sizes
__device__ float g_trace[BG];             // trace(out_adj) = sum_e dot(s[src],s[dst])

// ---------------- init: zero all accumulators ----------------
__global__ void initK() {
    int i = blockIdx.x * blockDim.x + threadIdx.x;
    int stride = gridDim.x * blockDim.x;
    for (int j = i; j < BG * CIN; j += stride) { g_s1[j] = 0.f; g_s2[j] = 0.f; }
    for (int j = i; j < NTOT; j += stride)     { g_cnt[j] = 0;  g_odeg[j] = 0; }
    for (int j = i; j < BG * KC * HID; j += stride) g_outacc[j] = 0.f;
    for (int j = i; j < BG * KC * KC; j += stride)  g_ssacc[j] = 0.f;
    for (int j = i; j < BG * KC; j += stride) { g_caacc[j] = 0.f; g_csacc[j] = 0.f; }
    if (i < BG) g_trace[i] = 0.f;
}

// ---------------- GraphNorm stats: per-(graph,channel) sum(x), sum(x^2) ----------------
__global__ void statsK(const float* __restrict__ x) {
    int b = blockIdx.x, chunk = blockIdx.y;         // grid (16, 8)
    int tid = threadIdx.x;                          // 256 threads
    int c = tid & 63, rsub = tid >> 6;              // 4 threads per channel
    int row0 = b * NPG + chunk * 256;
    float s1 = 0.f, s2 = 0.f;
    for (int r = rsub; r < 256; r += 4) {
        float v = x[(row0 + r) * CIN + c];
        s1 += v; s2 += v * v;
    }
    __shared__ float sh1[256], sh2[256];
    sh1[tid] = s1; sh2[tid] = s2;
    __syncthreads();
    if (rsub == 0) {
        s1 = sh1[c] + sh1[64 + c] + sh1[128 + c] + sh1[192 + c];
        s2 = sh2[c] + sh2[64 + c] + sh2[128 + c] + sh2[192 + c];
        atomicAdd(&g_s1[b * CIN + c], s1);
        atomicAdd(&g_s2[b * CIN + c], s2);
    }
}

// ---------------- fold GN into affine per (graph, channel): h = a*x + b ----------------
__global__ void abK(const float* __restrict__ gw, const float* __restrict__ gb,
                    const float* __restrict__ gms) {
    int i = blockIdx.x * blockDim.x + threadIdx.x;
    if (i >= BG * CIN) return;
    int c = i & 63;
    float inv_n = 1.f / (float)NPG;
    float mean = g_s1[i] * inv_n;
    float ex2  = g_s2[i] * inv_n;
    float ms = gms[c];
    // var of (x - ms*mean) = E[x^2] - 2*ms*mean^2 + ms^2*mean^2
    float var = ex2 - 2.f * ms * mean * mean + ms * ms * mean * mean;
    float rstd = rsqrtf(var + 1e-5f);
    float a = gw[c] * rstd;
    g_na[i] = a;
    g_nb[i] = gb[c] - a * ms * mean;
}

// ---------------- edge pass: build per-dst src lists + out-degrees ----------------
__global__ void edgeK(const int* __restrict__ ei) {
    int e = blockIdx.x * blockDim.x + threadIdx.x;
    if (e >= NE) return;
    int s = ei[e];
    int d = ei[NE + e];
    int pos = atomicAdd(&g_cnt[d], 1);
    if (pos < CAP) g_inlist[d * CAP + pos] = s;
    atomicAdd(&g_odeg[s], 1);
}

__global__ void dinvK() {
    int i = blockIdx.x * blockDim.x + threadIdx.x;
    if (i >= NTOT) return;
    g_dinv[i] = rsqrtf((float)(g_cnt[i] + 1));   // +1 self loop
    g_odegf[i] = (float)g_odeg[i];
}

// ---------------- fused GraphNorm + (h @ w1) : [NT,64]@[64,128] ----------------
__global__ __launch_bounds__(256) void gemm1K(const float* __restrict__ x,
                                              const float* __restrict__ w1) {
    __shared__ float shh[64][64];    // 16 KB
    __shared__ float shw[64][128];   // 32 KB  (total = 48 KB)
    int tid = threadIdx.x;
    int r0 = blockIdx.x * 64;
    int g = r0 / NPG;                // whole block in one graph (2048 % 64 == 0)

    // normalize-on-load: channel is fixed per thread across iterations
    int cl = tid & 63;
    float a = g_na[g * CIN + cl];
    float b = g_nb[g * CIN + cl];
    #pragma unroll
    for (int i = 0; i < 16; i++) {
        int idx = tid + 256 * i;
        int r = idx >> 6;
        shh[r][cl] = a * x[(r0 + r) * CIN + cl] + b;
    }
    int cw = tid & 127;
    #pragma unroll
    for (int i = 0; i < 32; i++) {             // 32 iters x 256 = 8192 = 64*128
        int idx = tid + 256 * i;
        int k = idx >> 7;
        shw[k][cw] = w1[idx];
    }
    __syncthreads();

    int tx = tid & 31, ty = tid >> 5;     // 8x4 register tile per thread
    float acc[8][4];
    #pragma unroll
    for (int rr = 0; rr < 8; rr++)
        #pragma unroll
        for (int cc = 0; cc < 4; cc++) acc[rr][cc] = 0.f;

    #pragma unroll 4
    for (int k = 0; k < 64; k++) {
        float wv[4];
        #pragma unroll
        for (int cc = 0; cc < 4; cc++) wv[cc] = shw[k][tx + 32 * cc];
        #pragma unroll
        for (int rr = 0; rr < 8; rr++) {
            float hv = shh[ty + 8 * rr][k];
            #pragma unroll
            for (int cc = 0; cc < 4; cc++) acc[rr][cc] += hv * wv[cc];
        }
    }
    #pragma unroll
    for (int rr = 0; rr < 8; rr++) {
        int row = r0 + ty + 8 * rr;
        #pragma unroll
        for (int cc = 0; cc < 4; cc++)
            g_hw[row * HID + tx + 32 * cc] = acc[rr][cc];
    }
}

// ---------------- GCN aggregation (gather by dst) + bias + selu ----------------
__global__ __launch_bounds__(128) void aggK(const float* __restrict__ b1) {
    __shared__ int   ssrc[CAP];
    __shared__ float swt[CAP];
    int i = blockIdx.x;
    int c = threadIdx.x;
    int cnt = g_cnt[i];
    if (cnt > CAP) cnt = CAP;
    float di = g_dinv[i];
    for (int j = c; j < cnt; j += 128) {
        int s = g_inlist[i * CAP + j];
        ssrc[j] = s;
        swt[j] = di * g_dinv[s];
    }
    __syncthreads();
    float acc = di * di * g_hw[i * HID + c];   // self loop
    // 4-way unrolled gather: keeps >=4 independent LDGs in flight (MLP>=4)
    int j = 0;
    float a0 = 0.f, a1 = 0.f, a2 = 0.f, a3 = 0.f;
    for (; j + 4 <= cnt; j += 4) {
        float v0 = g_hw[ssrc[j + 0] * HID + c];
        float v1 = g_hw[ssrc[j + 1] * HID + c];
        float v2 = g_hw[ssrc[j + 2] * HID + c];
        float v3 = g_hw[ssrc[j + 3] * HID + c];
        a0 += swt[j + 0] * v0;
        a1 += swt[j + 1] * v1;
        a2 += swt[j + 2] * v2;
        a3 += swt[j + 3] * v3;
    }
    for (; j < cnt; j++)
        acc += swt[j] * g_hw[ssrc[j] * HID + c];
    acc += (a0 + a1) + (a2 + a3);
    acc += b1[c];
    acc = acc > 0.f ? SELU_SCALE * acc : SELU_SCALE * SELU_ALPHA * (__expf(acc) - 1.f);
    g_xd[i * HID + c] = acc;
}

// ---------------- s = softmax(xd @ w2 + b2) over K=32 ----------------
__global__ __launch_bounds__(256) void softmaxK(const float* __restrict__ w2,
                                                const float* __restrict__ b2,
                                                float* __restrict__ dout) {
    __shared__ float shw2[128][32];  // 16 KB
    __shared__ float shx[8][128];    // 4 KB
    int tid = threadIdx.x;
    int r0 = blockIdx.x * 8;
    #pragma unroll
    for (int i = 0; i < 16; i++) {
        int idx = tid + 256 * i;
        shw2[idx >> 5][idx & 31] = w2[idx];
    }
    #pragma unroll
    for (int i = 0; i < 4; i++) {
        int idx = tid + 256 * i;
        shx[idx >> 7][idx & 127] = g_xd[r0 * HID + idx];
    }
    __syncthreads();
    int tx = tid & 31, ty = tid >> 5;     // tx = cluster, ty = local row
    float acc = b2[tx];
    #pragma unroll 8
    for (int k = 0; k < 128; k++)
        acc += shx[ty][k] * shw2[k][tx];
    // softmax across the warp (32 lanes == 32 clusters)
    float mx = acc;
    #pragma unroll
    for (int o = 16; o; o >>= 1) mx = fmaxf(mx, __shfl_xor_sync(~0u, mx, o));
    float ev = __expf(acc - mx);
    float sum = ev;
    #pragma unroll
    for (int o = 16; o; o >>= 1) sum += __shfl_xor_sync(~0u, sum, o);
    float sv = ev / sum;
    int row = r0 + ty;
    g_sc[row * KC + tx] = sv;
    dout[BG * KC * HID + 1 + row * KC + tx] = sv;   // s output region
}

// ---------------- trace(out_adj) per graph: sum over edges of dot(s[src],s[dst]) ----------------
__global__ __launch_bounds__(256) void traceK(const int* __restrict__ ei) {
    int tid = threadIdx.x;
    int warp = tid >> 5, lane = tid & 31;
    int base = blockIdx.x * 1024 + warp * 128;
    float part = 0.f;
    int g = -1;
    #pragma unroll 4
    for (int j = 0; j < 128; j++) {
        int e = base + j;
        int s = ei[e], d = ei[NE + e];
        g = s >> 11;                       // graph id from node id
        part += g_sc[s * KC + lane] * g_sc[d * KC + lane];
    }
    #pragma unroll
    for (int o = 16; o; o >>= 1) part += __shfl_xor_sync(~0u, part, o);
    __shared__ float wsum[8];
    __shared__ int   wg[8];
    if (lane == 0) { wsum[warp] = part; wg[warp] = g; }
    __syncthreads();
    if (tid == 0) {
        // NOTE: per-warp graph attribution may be approximate across graph
        // boundaries, but spectral loss depends only on sum_b trace_b because
        // m is uniform across graphs — so this is exact for the final loss.
        #pragma unroll
        for (int w = 0; w < 8; w++) atomicAdd(&g_trace[wg[w]], wsum[w]);
    }
}

// ---------------- pooling partials: s^T@xd, s^T@s, s^T@deg, colsum(s) ----------------
__global__ __launch_bounds__(256) void poolK() {
    __shared__ float shs[128][32];    // 16 KB
    __shared__ float shdeg[128];
    int tid = threadIdx.x;
    int b = blockIdx.x, ch = blockIdx.y;       // grid (16, 16): 128-node chunks
    int n0 = b * NPG + ch * 128;
    #pragma unroll
    for (int i = 0; i < 16; i++) {
        int idx = tid + 256 * i;
        shs[idx >> 5][idx & 31] = g_sc[n0 * KC + idx];
    }
    if (tid < 128) shdeg[tid] = g_odegf[n0 + tid];
    __syncthreads();

    // out partial: thread (ty,tx) computes 16 clusters x 1 feature
    int tx = tid & 127, ty = tid >> 7;
    float acc[16];
    #pragma unroll
    for (int kk = 0; kk < 16; kk++) acc[kk] = 0.f;
    for (int n = 0; n < 128; n++) {
        float xv = g_xd[(n0 + n) * HID + tx];
        #pragma unroll
        for (int kk = 0; kk < 16; kk++)
            acc[kk] += shs[n][ty * 16 + kk] * xv;
    }
    #pragma unroll
    for (int kk = 0; kk < 16; kk++)
        atomicAdd(&g_outacc[(b * KC + ty * 16 + kk) * HID + tx], acc[kk]);

    // ss partial: 1024 (k,l) outputs, 4 per thread
    for (int p = tid; p < KC * KC; p += 256) {
        int k = p >> 5, l = p & 31;
        float v = 0.f;
        for (int n = 0; n < 128; n++) v += shs[n][k] * shs[n][l];
        atomicAdd(&g_ssacc[b * KC * KC + p], v);
    }
    // ca / cluster_size partials
    if (tid < KC) {
        float ca = 0.f, cs = 0.f;
        for (int n = 0; n < 128; n++) {
            float sv = shs[n][tid];
            ca += sv * shdeg[n];
            cs += sv;
        }
        atomicAdd(&g_caacc[b * KC + tid], ca);
        atomicAdd(&g_csacc[b * KC + tid], cs);
    }
}

// ---------------- final loss: spectral + ortho + cluster ----------------
__global__ void lossK(float* __restrict__ dout) {
    __shared__ float shl[BG];
    int tid = threadIdx.x;                 // 512 threads = 16 warps, warp b = graph b
    int b = tid >> 5, lane = tid & 31;
    float ssq = 0.f, tr = 0.f;
    for (int p = lane; p < KC * KC; p += 32) {
        float v = g_ssacc[b * KC * KC + p];
        ssq += v * v;
        if ((p >> 5) == (p & 31)) tr += v;
    }
    float cav = g_caacc[b * KC + lane];
    float csv = g_csacc[b * KC + lane];
    float ca2 = cav * cav, cs2 = csv * csv;
    #pragma unroll
    for (int o = 16; o; o >>= 1) {
        ssq += __shfl_xor_sync(~0u, ssq, o);
        tr  += __shfl_xor_sync(~0u, tr, o);
        ca2 += __shfl_xor_sync(~0u, ca2, o);
        cs2 += __shfl_xor_sync(~0u, cs2, o);
    }
    if (lane == 0) {
        const float m = (float)(NPG * 16 / 2);   // N*DEG/2 = 16384 per graph
        float spectral = -(g_trace[b] - ca2 / (2.f * m)) / (2.f * m);
        float fro = sqrtf(ssq);
        float ortho = sqrtf(fmaxf(2.f - 2.f * tr / (fro * SQRT_K), 0.f));
        float cluster = sqrtf(cs2) / (float)NPG * SQRT_K - 1.f;
        shl[b] = spectral + ortho + cluster;
    }
    __syncthreads();
    if (tid == 0) {
        float t = 0.f;
        #pragma unroll
        for (int bb = 0; bb < BG; bb++) t += shl[bb];
        dout[BG * KC * HID] = t / (float)BG;
    }
}

// ---------------- selu + log_softmax over F=128 for out ----------------
__global__ __launch_bounds__(128) void outK(float* __restrict__ dout) {
    int row = blockIdx.x;          // b*32 + k  (512 rows)
    int tid = threadIdx.x;
    float v = g_outacc[row * HID + tid];
    v = v > 0.f ? SELU_SCALE * v : SELU_SCALE * SELU_ALPHA * (__expf(v) - 1.f);
    __shared__ float red[128];
    red[tid] = v;
    __syncthreads();
    for (int s = 64; s; s >>= 1) {
        if (tid < s) red[tid] = fmaxf(red[tid], red[tid + s]);
        __syncthreads();
    }
    float mx = red[0];
    __syncthreads();
    red[tid] = __expf(v - mx);
    __syncthreads();
    for (int s = 64; s; s >>= 1) {
        if (tid < s) red[tid] += red[tid + s];
        __syncthreads();
    }
    dout[row * HID + tid] = v - mx - logf(red[0]);
}

// ---------------- launch ----------------
extern "C" void kernel_launch(void* const* d_in, const int* in_sizes, int n_in,
                              void* d_out, int out_size) {
    const float* x = nullptr;
    const int* ei = nullptr;
    const float *gw = nullptr, *gb = nullptr, *gms = nullptr;
    const float *w1 = nullptr, *b1 = nullptr, *w2 = nullptr, *b2 = nullptr;
    int n64 = 0;
    for (int i = 0; i < n_in; i++) {
        int sz = in_sizes[i];
        const void* p = d_in[i];
        if (sz == NTOT * CIN)      x  = (const float*)p;
        else if (sz == 2 * NE)     ei = (const int*)p;
        else if (sz == NTOT)       { /* batch: uniform, unused */ }
        else if (sz == CIN) {
            if (n64 == 0) gw = (const float*)p;
            else if (n64 == 1) gb = (const float*)p;
            else gms = (const float*)p;
            n64++;
        }
        else if (sz == CIN * HID)  w1 = (const float*)p;
        else if (sz == HID)        b1 = (const float*)p;
        else if (sz == HID * KC)   w2 = (const float*)p;
        else if (sz == KC)         b2 = (const float*)p;
    }
    float* dout = (float*)d_out;

    initK<<<512, 256>>>();
    statsK<<<dim3(BG, 8), 256>>>(x);
    abK<<<4, 256>>>(gw, gb, gms);
    edgeK<<<NE / 256, 256>>>(ei);
    dinvK<<<NTOT / 256, 256>>>();
    gemm1K<<<NTOT / 64, 256>>>(x, w1);
    aggK<<<NTOT, 128>>>(b1);
    softmaxK<<<NTOT / 8, 256>>>(w2, b2, dout);
    traceK<<<NE / 1024, 256>>>(ei);
    poolK<<<dim3(BG, 16), 256>>>();
    lossK<<<1, 512>>>(dout);
    outK<<<BG * KC, 128>>>(dout);
}

// round 10
// speedup vs baseline: 1.1928x; 1.1928x over previous
#include <cuda_runtime.h>

// Problem constants
#define NTOT 32768      // total nodes (B*N)
#define BG   16         // graphs
#define NPG  2048       // nodes per graph
#define CIN  64
#define HID  128
#define KC   32
#define NE   524288     // edges
#define CAP  192        // per-node in-edge capacity (Poisson(16); 192 is astronomically safe)

#define SELU_SCALE 1.0507009873554805f
#define SELU_ALPHA 1.6732632423543772f
#define SQRT_K     5.656854249492380f   // sqrt(32)

__device__ __forceinline__ float selu(float v) {
    return v > 0.f ? SELU_SCALE * v : SELU_SCALE * SELU_ALPHA * (__expf(v) - 1.f);
}

// ---------------- device scratch (no runtime allocation allowed) ----------------
__device__ float g_s1[BG * CIN];
__device__ float g_s2[BG * CIN];
__device__ float g_na[BG * CIN];          // per-(graph,ch) affine a:  h = a*x + b
__device__ float g_nb[BG * CIN];
__device__ float g_hw[NTOT * HID];        // 16 MB  (normalized x) @ w1
__device__ float g_xd[NTOT * HID];        // 16 MB  post-GCN features
__device__ float g_sc[NTOT * KC];         // 4 MB   soft assignments s
__device__ int   g_cnt[NTOT];             // in-degree (excl self loop)
__device__ int   g_odeg[NTOT];            // out-degree (for DMoN degrees)
__device__ float g_dinv[NTOT];
__device__ float g_odegf[NTOT];
__device__ int   g_inlist[NTOT * CAP];    // 25 MB  CSR-ish slots: srcs per dst
__device__ float g_outacc[BG * KC * HID]; // s^T @ xd accumulators
__device__ float g_ssacc[BG * KC * KC];   // s^T @ s
__device__ float g_caacc[BG * KC];        // s^T @ degrees
__device__ float g_csacc[BG * KC];        // cluster sizes
__device__ float g_trace[BG];             // trace(out_adj) = sum_e dot(s[src],s[dst])

// ---------------- init: zero all accumulators ----------------
__global__ void initK() {
    int i = blockIdx.x * blockDim.x + threadIdx.x;
    int stride = gridDim.x * blockDim.x;
    for (int j = i; j < BG * CIN; j += stride) { g_s1[j] = 0.f; g_s2[j] = 0.f; }
    for (int j = i; j < NTOT; j += stride)     { g_cnt[j] = 0;  g_odeg[j] = 0; }
    for (int j = i; j < BG * KC * HID; j += stride) g_outacc[j] = 0.f;
    for (int j = i; j < BG * KC * KC; j += stride)  g_ssacc[j] = 0.f;
    for (int j = i; j < BG * KC; j += stride) { g_caacc[j] = 0.f; g_csacc[j] = 0.f; }
    if (i < BG) g_trace[i] = 0.f;
}

// ---------------- GraphNorm stats: per-(graph,channel) sum(x), sum(x^2) ----------------
__global__ void statsK(const float* __restrict__ x) {
    int b = blockIdx.x, chunk = blockIdx.y;         // grid (16, 8)
    int tid = threadIdx.x;                          // 256 threads
    int c = tid & 63, rsub = tid >> 6;              // 4 threads per channel
    int row0 = b * NPG + chunk * 256;
    float s1 = 0.f, s2 = 0.f;
    for (int r = rsub; r < 256; r += 4) {
        float v = x[(row0 + r) * CIN + c];
        s1 += v; s2 += v * v;
    }
    __shared__ float sh1[256], sh2[256];
    sh1[tid] = s1; sh2[tid] = s2;
    __syncthreads();
    if (rsub == 0) {
        s1 = sh1[c] + sh1[64 + c] + sh1[128 + c] + sh1[192 + c];
        s2 = sh2[c] + sh2[64 + c] + sh2[128 + c] + sh2[192 + c];
        atomicAdd(&g_s1[b * CIN + c], s1);
        atomicAdd(&g_s2[b * CIN + c], s2);
    }
}

// ---------------- fold GN into affine per (graph, channel): h = a*x + b ----------------
__global__ void abK(const float* __restrict__ gw, const float* __restrict__ gb,
                    const float* __restrict__ gms) {
    int i = blockIdx.x * blockDim.x + threadIdx.x;
    if (i >= BG * CIN) return;
    int c = i & 63;
    float inv_n = 1.f / (float)NPG;
    float mean = g_s1[i] * inv_n;
    float ex2  = g_s2[i] * inv_n;
    float ms = gms[c];
    float var = ex2 - 2.f * ms * mean * mean + ms * ms * mean * mean;
    float rstd = rsqrtf(var + 1e-5f);
    float a = gw[c] * rstd;
    g_na[i] = a;
    g_nb[i] = gb[c] - a * ms * mean;
}

// ---------------- edge pass: 4 edges/thread via int4 (8 atomics in flight) ----------------
__global__ void edgeK(const int* __restrict__ ei) {
    int t = blockIdx.x * blockDim.x + threadIdx.x;     // NE/4 threads
    int4 s4 = ((const int4*)ei)[t];
    int4 d4 = ((const int4*)(ei + NE))[t];
    int p0 = atomicAdd(&g_cnt[d4.x], 1);
    int p1 = atomicAdd(&g_cnt[d4.y], 1);
    int p2 = atomicAdd(&g_cnt[d4.z], 1);
    int p3 = atomicAdd(&g_cnt[d4.w], 1);
    atomicAdd(&g_odeg[s4.x], 1);
    atomicAdd(&g_odeg[s4.y], 1);
    atomicAdd(&g_odeg[s4.z], 1);
    atomicAdd(&g_odeg[s4.w], 1);
    if (p0 < CAP) g_inlist[d4.x * CAP + p0] = s4.x;
    if (p1 < CAP) g_inlist[d4.y * CAP + p1] = s4.y;
    if (p2 < CAP) g_inlist[d4.z * CAP + p2] = s4.z;
    if (p3 < CAP) g_inlist[d4.w * CAP + p3] = s4.w;
}

__global__ void dinvK() {
    int i = blockIdx.x * blockDim.x + threadIdx.x;
    if (i >= NTOT) return;
    g_dinv[i] = rsqrtf((float)(g_cnt[i] + 1));   // +1 self loop
    g_odegf[i] = (float)g_odeg[i];
}

// ---------------- fused GraphNorm + (h @ w1) : [NT,64]@[64,128] (FMA-bound) ----------------
__global__ __launch_bounds__(256) void gemm1K(const float* __restrict__ x,
                                              const float* __restrict__ w1) {
    __shared__ float shh[64][64];    // 16 KB
    __shared__ float shw[64][128];   // 32 KB  (total = 48 KB)
    int tid = threadIdx.x;
    int r0 = blockIdx.x * 64;
    int g = r0 / NPG;

    int cl = tid & 63;
    float a = g_na[g * CIN + cl];
    float b = g_nb[g * CIN + cl];
    #pragma unroll
    for (int i = 0; i < 16; i++) {
        int idx = tid + 256 * i;
        int r = idx >> 6;
        shh[r][cl] = a * x[(r0 + r) * CIN + cl] + b;
    }
    int cw = tid & 127;
    #pragma unroll
    for (int i = 0; i < 32; i++) {
        int idx = tid + 256 * i;
        int k = idx >> 7;
        shw[k][cw] = w1[idx];
    }
    __syncthreads();

    int tx = tid & 31, ty = tid >> 5;     // 8x4 register tile per thread
    float acc[8][4];
    #pragma unroll
    for (int rr = 0; rr < 8; rr++)
        #pragma unroll
        for (int cc = 0; cc < 4; cc++) acc[rr][cc] = 0.f;

    #pragma unroll 4
    for (int k = 0; k < 64; k++) {
        float wv[4];
        #pragma unroll
        for (int cc = 0; cc < 4; cc++) wv[cc] = shw[k][tx + 32 * cc];
        #pragma unroll
        for (int rr = 0; rr < 8; rr++) {
            float hv = shh[ty + 8 * rr][k];
            #pragma unroll
            for (int cc = 0; cc < 4; cc++) acc[rr][cc] += hv * wv[cc];
        }
    }
    #pragma unroll
    for (int rr = 0; rr < 8; rr++) {
        int row = r0 + ty + 8 * rr;
        #pragma unroll
        for (int cc = 0; cc < 4; cc++)
            g_hw[row * HID + tx + 32 * cc] = acc[rr][cc];
    }
}

// ---------------- GCN aggregation: warp per node, float4 gathers ----------------
__global__ __launch_bounds__(256) void aggK(const float* __restrict__ b1) {
    __shared__ int   ssrc[8][CAP];
    __shared__ float swt[8][CAP];     // 12 KB
    int warp = threadIdx.x >> 5, lane = threadIdx.x & 31;
    int i = blockIdx.x * 8 + warp;
    int cnt = g_cnt[i]; if (cnt > CAP) cnt = CAP;
    float di = g_dinv[i];
    for (int j = lane; j < cnt; j += 32) {
        int s = g_inlist[i * CAP + j];
        ssrc[warp][j] = s;
        swt[warp][j] = di * g_dinv[s];
    }
    __syncwarp();
    const float4* hw4 = (const float4*)g_hw;   // lane covers channels lane*4..+3
    float4 self = hw4[i * 32 + lane];
    float w0 = di * di;
    float ax = w0 * self.x, ay = w0 * self.y, az = w0 * self.z, aw = w0 * self.w;
    int j = 0;
    for (; j + 2 <= cnt; j += 2) {
        int s0 = ssrc[warp][j], s1 = ssrc[warp][j + 1];
        float wa = swt[warp][j], wb = swt[warp][j + 1];
        float4 v0 = hw4[s0 * 32 + lane];
        float4 v1 = hw4[s1 * 32 + lane];
        ax += wa * v0.x + wb * v1.x;
        ay += wa * v0.y + wb * v1.y;
        az += wa * v0.z + wb * v1.z;
        aw += wa * v0.w + wb * v1.w;
    }
    if (j < cnt) {
        float wa = swt[warp][j];
        float4 v0 = hw4[ssrc[warp][j] * 32 + lane];
        ax += wa * v0.x; ay += wa * v0.y; az += wa * v0.z; aw += wa * v0.w;
    }
    float4 bb = ((const float4*)b1)[lane];
    float4 r;
    r.x = selu(ax + bb.x);
    r.y = selu(ay + bb.y);
    r.z = selu(az + bb.z);
    r.w = selu(aw + bb.w);
    ((float4*)g_xd)[i * 32 + lane] = r;
}

// ---------------- s = softmax(xd @ w2 + b2): register-tiled GEMM + warp softmax ----------------
__global__ __launch_bounds__(256) void softmaxK(const float* __restrict__ w2,
                                                const float* __restrict__ b2,
                                                float* __restrict__ dout) {
    __shared__ float shx[128 * 64];   // k-major x tile: shx[k*64 + row]   32 KB
    __shared__ float shw[128 * 32];   // shw[k*32 + c] 16 KB; reused for logits [64][33]
    int tid = threadIdx.x;
    int r0 = blockIdx.x * 64;         // grid 512

    {   // fill w2 (4096 floats)
        const float4* w4 = (const float4*)w2;
        float4* s4 = (float4*)shw;
        #pragma unroll
        for (int i = 0; i < 4; i++) s4[tid + 256 * i] = w4[tid + 256 * i];
    }
    {   // fill x transposed (k-major)
        int row = tid >> 2, kq = tid & 3;
        const float4* xd4 = (const float4*)g_xd;
        #pragma unroll
        for (int it = 0; it < 8; it++) {
            float4 v = xd4[(r0 + row) * 32 + kq * 8 + it];
            int k = kq * 32 + it * 4;
            shx[(k + 0) * 64 + row] = v.x;
            shx[(k + 1) * 64 + row] = v.y;
            shx[(k + 2) * 64 + row] = v.z;
            shx[(k + 3) * 64 + row] = v.w;
        }
    }
    __syncthreads();

    // GEMM: thread = (tx: 4 clusters, ty: 2 rows)
    int tx = tid & 7, ty = tid >> 3;
    float a00=0.f,a01=0.f,a02=0.f,a03=0.f,a10=0.f,a11=0.f,a12=0.f,a13=0.f;
    #pragma unroll 8
    for (int k = 0; k < 128; k++) {
        float4 wv = *(const float4*)&shw[k * 32 + tx * 4];
        float h0 = shx[k * 64 + ty * 2];
        float h1 = shx[k * 64 + ty * 2 + 1];
        a00 += h0 * wv.x; a01 += h0 * wv.y; a02 += h0 * wv.z; a03 += h0 * wv.w;
        a10 += h1 * wv.x; a11 += h1 * wv.y; a12 += h1 * wv.z; a13 += h1 * wv.w;
    }
    __syncthreads();                      // shw free; reuse as logits [64][33]
    float* lg = shw;
    float4 bv = ((const float4*)b2)[tx];
    int c0 = tx * 4;
    int rowa = ty * 2, rowb = ty * 2 + 1;
    lg[rowa * 33 + c0 + 0] = a00 + bv.x;
    lg[rowa * 33 + c0 + 1] = a01 + bv.y;
    lg[rowa * 33 + c0 + 2] = a02 + bv.z;
    lg[rowa * 33 + c0 + 3] = a03 + bv.w;
    lg[rowb * 33 + c0 + 0] = a10 + bv.x;
    lg[rowb * 33 + c0 + 1] = a11 + bv.y;
    lg[rowb * 33 + c0 + 2] = a12 + bv.z;
    lg[rowb * 33 + c0 + 3] = a13 + bv.w;
    __syncthreads();

    // warp softmax: warp w handles rows w*8..w*8+7, lane = cluster
    int warp = tid >> 5, lane = tid & 31;
    #pragma unroll
    for (int r = 0; r < 8; r++) {
        int row = warp * 8 + r;
        float v = lg[row * 33 + lane];
        float mx = v;
        #pragma unroll
        for (int o = 16; o; o >>= 1) mx = fmaxf(mx, __shfl_xor_sync(~0u, mx, o));
        float ev = __expf(v - mx);
        float sum = ev;
        #pragma unroll
        for (int o = 16; o; o >>= 1) sum += __shfl_xor_sync(~0u, sum, o);
        float sv = ev / sum;
        int grow = r0 + row;
        g_sc[grow * KC + lane] = sv;
        dout[BG * KC * HID + 1 + grow * KC + lane] = sv;
    }
}

// ---------------- trace: 4 edges per warp-step, 8 lanes x float4 per row ----------------
__global__ __launch_bounds__(256) void traceK(const int* __restrict__ ei) {
    int tid = threadIdx.x, warp = tid >> 5, lane = tid & 31;
    int sub = lane >> 3, q = lane & 7;
    const float4* sc4 = (const float4*)g_sc;
    int base = blockIdx.x * 4096 + warp * 512;    // grid 128
    float part = 0.f;
    int gs = 0;
    #pragma unroll 2
    for (int j0 = 0; j0 < 512; j0 += 4) {
        int e = base + j0 + sub;
        int s = ei[e], d = ei[NE + e];
        gs = s;
        float4 a = sc4[s * 8 + q];
        float4 b = sc4[d * 8 + q];
        part += a.x * b.x + a.y * b.y + a.z * b.z + a.w * b.w;
    }
    #pragma unroll
    for (int o = 16; o; o >>= 1) part += __shfl_xor_sync(~0u, part, o);
    // graph attribution per warp is approximate near graph boundaries, but the
    // spectral loss depends only on sum_b trace_b (m uniform) -> exact.
    if (lane == 0) atomicAdd(&g_trace[gs >> 11], part);
}

// ---------------- pooling: register-tiled s^T@xd, s^T@s, s^T@deg, colsum(s) ----------------
__global__ __launch_bounds__(256) void poolK() {
    __shared__ float shs[64 * 32];    // 8 KB
    __shared__ float shx[64 * 128];   // 32 KB (total 40 KB)
    __shared__ float shdeg[64];
    int tid = threadIdx.x;
    int b = blockIdx.x, ch = blockIdx.y;       // grid (16, 16): 128-node chunks, 2 sub of 64
    int tx = tid & 31, ty = tid >> 5;          // out tile: feats tx*4.., clusters ty*4..
    int sk = tid >> 3, sl = (tid & 7) * 4;     // ss tile
    float acc[4][4];
    #pragma unroll
    for (int c = 0; c < 4; c++)
        #pragma unroll
        for (int f = 0; f < 4; f++) acc[c][f] = 0.f;
    float ss0 = 0.f, ss1 = 0.f, ss2 = 0.f, ss3 = 0.f;
    float ca = 0.f, cs = 0.f;

    for (int sub = 0; sub < 2; sub++) {
        int n0 = b * NPG + ch * 128 + sub * 64;
        __syncthreads();
        {   // fill s tile (2048 floats)
            const float4* s4 = (const float4*)(g_sc + n0 * KC);
            float4* d4 = (float4*)shs;
            d4[tid] = s4[tid];
            d4[tid + 256] = s4[tid + 256];
        }
        {   // fill xd tile (8192 floats)
            const float4* x4 = (const float4*)(g_xd + n0 * HID);
            float4* d4 = (float4*)shx;
            #pragma unroll
            for (int i2 = 0; i2 < 8; i2++) d4[tid + 256 * i2] = x4[tid + 256 * i2];
        }
        if (tid < 64) shdeg[tid] = g_odegf[n0 + tid];
        __syncthreads();

        #pragma unroll 4
        for (int n = 0; n < 64; n++) {
            float4 sv = *(const float4*)&shs[n * 32 + ty * 4];
            float4 xv = *(const float4*)&shx[n * 128 + tx * 4];
            acc[0][0] += sv.x * xv.x; acc[0][1] += sv.x * xv.y; acc[0][2] += sv.x * xv.z; acc[0][3] += sv.x * xv.w;
            acc[1][0] += sv.y * xv.x; acc[1][1] += sv.y * xv.y; acc[1][2] += sv.y * xv.z; acc[1][3] += sv.y * xv.w;
            acc[2][0] += sv.z * xv.x; acc[2][1] += sv.z * xv.y; acc[2][2] += sv.z * xv.z; acc[2][3] += sv.z * xv.w;
            acc[3][0] += sv.w * xv.x; acc[3][1] += sv.w * xv.y; acc[3][2] += sv.w * xv.z; acc[3][3] += sv.w * xv.w;
        }
        #pragma unroll 4
        for (int n = 0; n < 64; n++) {
            float a = shs[n * 32 + sk];
            float4 sb = *(const float4*)&shs[n * 32 + sl];
            ss0 += a * sb.x; ss1 += a * sb.y; ss2 += a * sb.z; ss3 += a * sb.w;
        }
        if (tid < 32) {
            for (int n = 0; n < 64; n++) {
                float sv = shs[n * 32 + tid];
                ca += sv * shdeg[n];
                cs += sv;
            }
        }
    }
    #pragma unroll
    for (int c = 0; c < 4; c++)
        #pragma unroll
        for (int f = 0; f < 4; f++)
            atomicAdd(&g_outacc[(b * KC + ty * 4 + c) * HID + tx * 4 + f], acc[c][f]);
    atomicAdd(&g_ssacc[b * KC * KC + sk * KC + sl + 0], ss0);
    atomicAdd(&g_ssacc[b * KC * KC + sk * KC + sl + 1], ss1);
    atomicAdd(&g_ssacc[b * KC * KC + sk * KC + sl + 2], ss2);
    atomicAdd(&g_ssacc[b * KC * KC + sk * KC + sl + 3], ss3);
    if (tid < 32) { atomicAdd(&g_caacc[b * KC + tid], ca); atomicAdd(&g_csacc[b * KC + tid], cs); }
}

// ---------------- final loss: spectral + ortho + cluster ----------------
__global__ void lossK(float* __restrict__ dout) {
    __shared__ float shl[BG];
    int tid = threadIdx.x;                 // 512 threads = 16 warps, warp b = graph b
    int b = tid >> 5, lane = tid & 31;
    float ssq = 0.f, tr = 0.f;
    for (int p = lane; p < KC * KC; p += 32) {
        float v = g_ssacc[b * KC * KC + p];
        ssq += v * v;
        if ((p >> 5) == (p & 31)) tr += v;
    }
    float cav = g_caacc[b * KC + lane];
    float csv = g_csacc[b * KC + lane];
    float ca2 = cav * cav, cs2 = csv * csv;
    #pragma unroll
    for (int o = 16; o; o >>= 1) {
        ssq += __shfl_xor_sync(~0u, ssq, o);
        tr  += __shfl_xor_sync(~0u, tr, o);
        ca2 += __shfl_xor_sync(~0u, ca2, o);
        cs2 += __shfl_xor_sync(~0u, cs2, o);
    }
    if (lane == 0) {
        const float m = (float)(NPG * 16 / 2);   // N*DEG/2 = 16384 per graph
        float spectral = -(g_trace[b] - ca2 / (2.f * m)) / (2.f * m);
        float fro = sqrtf(ssq);
        float ortho = sqrtf(fmaxf(2.f - 2.f * tr / (fro * SQRT_K), 0.f));
        float cluster = sqrtf(cs2) / (float)NPG * SQRT_K - 1.f;
        shl[b] = spectral + ortho + cluster;
    }
    __syncthreads();
    if (tid == 0) {
        float t = 0.f;
        #pragma unroll
        for (int bb = 0; bb < BG; bb++) t += shl[bb];
        dout[BG * KC * HID] = t / (float)BG;
    }
}

// ---------------- selu + log_softmax over F=128 for out ----------------
__global__ __launch_bounds__(128) void outK(float* __restrict__ dout) {
    int row = blockIdx.x;          // b*32 + k  (512 rows)
    int tid = threadIdx.x;
    float v = g_outacc[row * HID + tid];
    v = selu(v);
    __shared__ float red[128];
    red[tid] = v;
    __syncthreads();
    for (int s = 64; s; s >>= 1) {
        if (tid < s) red[tid] = fmaxf(red[tid], red[tid + s]);
        __syncthreads();
    }
    float mx = red[0];
    __syncthreads();
    red[tid] = __expf(v - mx);
    __syncthreads();
    for (int s = 64; s; s >>= 1) {
        if (tid < s) red[tid] += red[tid + s];
        __syncthreads();
    }
    dout[row * HID + tid] = v - mx - logf(red[0]);
}

// ---------------- launch ----------------
extern "C" void kernel_launch(void* const* d_in, const int* in_sizes, int n_in,
                              void* d_out, int out_size) {
    const float* x = nullptr;
    const int* ei = nullptr;
    const float *gw = nullptr, *gb = nullptr, *gms = nullptr;
    const float *w1 = nullptr, *b1 = nullptr, *w2 = nullptr, *b2 = nullptr;
    int n64 = 0;
    for (int i = 0; i < n_in; i++) {
        int sz = in_sizes[i];
        const void* p = d_in[i];
        if (sz == NTOT * CIN)      x  = (const float*)p;
        else if (sz == 2 * NE)     ei = (const int*)p;
        else if (sz == NTOT)       { /* batch: uniform, unused */ }
        else if (sz == CIN) {
            if (n64 == 0) gw = (const float*)p;
            else if (n64 == 1) gb = (const float*)p;
            else gms = (const float*)p;
            n64++;
        }
        else if (sz == CIN * HID)  w1 = (const float*)p;
        else if (sz == HID)        b1 = (const float*)p;
        else if (sz == HID * KC)   w2 = (const float*)p;
        else if (sz == KC)         b2 = (const float*)p;
    }
    float* dout = (float*)d_out;

    initK<<<512, 256>>>();
    statsK<<<dim3(BG, 8), 256>>>(x);
    abK<<<4, 256>>>(gw, gb, gms);
    edgeK<<<NE / 4 / 256, 256>>>(ei);
    dinvK<<<NTOT / 256, 256>>>();
    gemm1K<<<NTOT / 64, 256>>>(x, w1);
    aggK<<<NTOT / 8, 256>>>(b1);
    softmaxK<<<NTOT / 64, 256>>>(w2, b2, dout);
    traceK<<<NE / 4096, 256>>>(ei);
    poolK<<<dim3(BG, 16), 256>>>();
    lossK<<<1, 512>>>(dout);
    outK<<<BG * KC, 128>>>(dout);
}

// round 15
// speedup vs baseline: 1.2639x; 1.0596x over previous
#include <cuda_runtime.h>

// Problem constants
#define NTOT 32768      // total nodes (B*N)
#define BG   16         // graphs
#define NPG  2048       // nodes per graph
#define CIN  64
#define HID  128
#define KC   32
#define NE   524288     // edges
#define CAP  192        // per-node in-edge capacity

#define SELU_SCALE 1.0507009873554805f
#define SELU_ALPHA 1.6732632423543772f
#define SQRT_K     5.656854249492380f   // sqrt(32)

__device__ __forceinline__ float selu(float v) {
    return v > 0.f ? SELU_SCALE * v : SELU_SCALE * SELU_ALPHA * (__expf(v) - 1.f);
}

// ---------------- device scratch ----------------
__device__ float g_ps1[BG * 8 * CIN];     // per-(graph,chunk) partial sum(x)
__device__ float g_ps2[BG * 8 * CIN];     // per-(graph,chunk) partial sum(x^2)
__device__ float g_na[BG * CIN];          // folded GN affine: h = a*x + b
__device__ float g_nb[BG * CIN];
__device__ float g_ah[NTOT * CIN];        // 8 MB  aggregated+normalized features (pre-GEMM)
__device__ float g_xd[NTOT * HID];        // 16 MB post-GCN features
__device__ float g_sc[NTOT * KC];         // 4 MB  soft assignments s
__device__ int   g_cnt[NTOT];             // in-degree (excl self loop)
__device__ int   g_odeg[NTOT];            // out-degree
__device__ float g_dinv[NTOT];
__device__ float g_odegf[NTOT];
__device__ int   g_inlist[NTOT * CAP];    // 25 MB per-dst src lists
__device__ float g_outacc[BG * KC * HID];
__device__ float g_ssacc[BG * KC * KC];
__device__ float g_caacc[BG * KC];
__device__ float g_csacc[BG * KC];
__device__ float g_trace[BG];

// ---------------- stats + zeroing: partial sums per (graph, chunk); zero accumulators ----------------
__global__ void statsK(const float* __restrict__ x) {
    int b = blockIdx.x, chunk = blockIdx.y;         // grid (16, 8)
    int tid = threadIdx.x;                          // 256 threads
    // zeroing: bijection over 32768 threads
    int gt = (b * 8 + chunk) * 256 + tid;
    g_cnt[gt] = 0; g_odeg[gt] = 0;
    g_outacc[gt] = 0.f; g_outacc[32768 + gt] = 0.f;
    if (gt < BG * KC * KC) g_ssacc[gt] = 0.f;
    if (gt < BG * KC) { g_caacc[gt] = 0.f; g_csacc[gt] = 0.f; }
    if (gt < BG) g_trace[gt] = 0.f;

    // partial sums over this block's 256 rows
    int c = tid & 63, rsub = tid >> 6;
    int row0 = b * NPG + chunk * 256;
    float s1 = 0.f, s2 = 0.f;
    for (int r = rsub; r < 256; r += 4) {
        float v = x[(row0 + r) * CIN + c];
        s1 += v; s2 += v * v;
    }
    __shared__ float sh1[256], sh2[256];
    sh1[tid] = s1; sh2[tid] = s2;
    __syncthreads();
    if (rsub == 0) {
        s1 = sh1[c] + sh1[64 + c] + sh1[128 + c] + sh1[192 + c];
        s2 = sh2[c] + sh2[64 + c] + sh2[128 + c] + sh2[192 + c];
        g_ps1[(b * 8 + chunk) * CIN + c] = s1;      // plain store: no atomics, no pre-zero
        g_ps2[(b * 8 + chunk) * CIN + c] = s2;
    }
}

// ---------------- edge pass: scalar, 1 edge/thread (measured faster than int4) ----------------
__global__ void edgeK(const int* __restrict__ ei) {
    int e = blockIdx.x * blockDim.x + threadIdx.x;
    if (e >= NE) return;
    int s = ei[e];
    int d = ei[NE + e];
    int pos = atomicAdd(&g_cnt[d], 1);
    if (pos < CAP) g_inlist[d * CAP + pos] = s;
    atomicAdd(&g_odeg[s], 1);
}

// ---------------- setup: dinv/odegf per node + GN affine from partials ----------------
__global__ void setupK(const float* __restrict__ gw, const float* __restrict__ gb,
                       const float* __restrict__ gms) {
    int i = blockIdx.x * blockDim.x + threadIdx.x;   // 32768 threads
    g_dinv[i] = rsqrtf((float)(g_cnt[i] + 1));       // +1 self loop
    g_odegf[i] = (float)g_odeg[i];
    if (i < BG * CIN) {
        int b = i >> 6, c = i & 63;
        float s1 = 0.f, s2 = 0.f;
        #pragma unroll
        for (int ch = 0; ch < 8; ch++) {
            s1 += g_ps1[(b * 8 + ch) * CIN + c];
            s2 += g_ps2[(b * 8 + ch) * CIN + c];
        }
        float inv_n = 1.f / (float)NPG;
        float mean = s1 * inv_n;
        float ex2  = s2 * inv_n;
        float ms = gms[c];
        float var = ex2 - 2.f * ms * mean * mean + ms * ms * mean * mean;
        float rstd = rsqrtf(var + 1e-5f);
        float a = gw[c] * rstd;
        g_na[i] = a;
        g_nb[i] = gb[c] - a * ms * mean;
    }
}

// ---------------- GCN aggregation over RAW x (64 ch): agg THEN affine THEN (later) GEMM ----------------
// A_hat(gn(x)) = a (.) A_hat(x) + (sum of weights) * b    -- affine commutes through linear agg
__global__ __launch_bounds__(256) void aggXK(const float* __restrict__ x) {
    __shared__ int   ssrc[8][CAP];
    __shared__ float swt[8][CAP];     // 12 KB
    int warp = threadIdx.x >> 5, lane = threadIdx.x & 31;
    int i = blockIdx.x * 8 + warp;
    int cnt = g_cnt[i]; if (cnt > CAP) cnt = CAP;
    float di = g_dinv[i];
    for (int j = lane; j < cnt; j += 32) {
        int s = g_inlist[i * CAP + j];
        ssrc[warp][j] = s;
        swt[warp][j] = di * g_dinv[s];
    }
    __syncwarp();
    const float2* x2 = (const float2*)x;      // lane covers channels lane*2, lane*2+1
    float2 self = x2[i * 32 + lane];
    float w0 = di * di;
    float Sx = w0 * self.x, Sy = w0 * self.y, sumw = w0;
    int j = 0;
    for (; j + 2 <= cnt; j += 2) {
        int s0 = ssrc[warp][j], s1 = ssrc[warp][j + 1];
        float wa = swt[warp][j], wb = swt[warp][j + 1];
        float2 v0 = x2[s0 * 32 + lane];
        float2 v1 = x2[s1 * 32 + lane];
        Sx += wa * v0.x + wb * v1.x;
        Sy += wa * v0.y + wb * v1.y;
        sumw += wa + wb;
    }
    if (j < cnt) {
        float wa = swt[warp][j];
        float2 v = x2[ssrc[warp][j] * 32 + lane];
        Sx += wa * v.x; Sy += wa * v.y; sumw += wa;
    }
    int g = i >> 11;
    float2 av = ((const float2*)g_na)[g * 32 + lane];
    float2 bv = ((const float2*)g_nb)[g * 32 + lane];
    float2 r;
    r.x = av.x * Sx + sumw * bv.x;
    r.y = av.y * Sy + sumw * bv.y;
    ((float2*)g_ah)[i * 32 + lane] = r;
}

// ---------------- GEMM: g_ah[NT,64] @ w1[64,128] + b1, selu -> g_xd ----------------
__global__ __launch_bounds__(256) void gemmK(const float* __restrict__ w1,
                                             const float* __restrict__ b1) {
    __shared__ float shh[64][64];    // 16 KB
    __shared__ float shw[64][128];   // 32 KB
    int tid = threadIdx.x;
    int r0 = blockIdx.x * 64;

    int cl = tid & 63;
    #pragma unroll
    for (int i = 0; i < 16; i++) {
        int idx = tid + 256 * i;
        int r = idx >> 6;
        shh[r][cl] = g_ah[(r0 + r) * CIN + cl];
    }
    int cw = tid & 127;
    #pragma unroll
    for (int i = 0; i < 32; i++) {
        int idx = tid + 256 * i;
        int k = idx >> 7;
        shw[k][cw] = w1[idx];
    }
    __syncthreads();

    int tx = tid & 31, ty = tid >> 5;     // 8x4 register tile
    float acc[8][4];
    #pragma unroll
    for (int rr = 0; rr < 8; rr++)
        #pragma unroll
        for (int cc = 0; cc < 4; cc++) acc[rr][cc] = 0.f;

    #pragma unroll 4
    for (int k = 0; k < 64; k++) {
        float wv[4];
        #pragma unroll
        for (int cc = 0; cc < 4; cc++) wv[cc] = shw[k][tx + 32 * cc];
        #pragma unroll
        for (int rr = 0; rr < 8; rr++) {
            float hv = shh[ty + 8 * rr][k];
            #pragma unroll
            for (int cc = 0; cc < 4; cc++) acc[rr][cc] += hv * wv[cc];
        }
    }
    float bb[4];
    #pragma unroll
    for (int cc = 0; cc < 4; cc++) bb[cc] = b1[tx + 32 * cc];
    #pragma unroll
    for (int rr = 0; rr < 8; rr++) {
        int row = r0 + ty + 8 * rr;
        #pragma unroll
        for (int cc = 0; cc < 4; cc++)
            g_xd[row * HID + tx + 32 * cc] = selu(acc[rr][cc] + bb[cc]);
    }
}

// ---------------- s = softmax(xd @ w2 + b2): register-tiled GEMM + warp softmax ----------------
__global__ __launch_bounds__(256) void softmaxK(const float* __restrict__ w2,
                                                const float* __restrict__ b2,
                                                float* __restrict__ dout) {
    __shared__ float shx[128 * 64];   // k-major x tile  32 KB
    __shared__ float shw[128 * 32];   // w2 16 KB; reused for logits [64][33]
    int tid = threadIdx.x;
    int r0 = blockIdx.x * 64;         // grid 512

    {
        const float4* w4 = (const float4*)w2;
        float4* s4 = (float4*)shw;
        #pragma unroll
        for (int i = 0; i < 4; i++) s4[tid + 256 * i] = w4[tid + 256 * i];
    }
    {
        int row = tid >> 2, kq = tid & 3;
        const float4* xd4 = (const float4*)g_xd;
        #pragma unroll
        for (int it = 0; it < 8; it++) {
            float4 v = xd4[(r0 + row) * 32 + kq * 8 + it];
            int k = kq * 32 + it * 4;
            shx[(k + 0) * 64 + row] = v.x;
            shx[(k + 1) * 64 + row] = v.y;
            shx[(k + 2) * 64 + row] = v.z;
            shx[(k + 3) * 64 + row] = v.w;
        }
    }
    __syncthreads();

    int tx = tid & 7, ty = tid >> 3;
    float a00=0.f,a01=0.f,a02=0.f,a03=0.f,a10=0.f,a11=0.f,a12=0.f,a13=0.f;
    #pragma unroll 8
    for (int k = 0; k < 128; k++) {
        float4 wv = *(const float4*)&shw[k * 32 + tx * 4];
        float h0 = shx[k * 64 + ty * 2];
        float h1 = shx[k * 64 + ty * 2 + 1];
        a00 += h0 * wv.x; a01 += h0 * wv.y; a02 += h0 * wv.z; a03 += h0 * wv.w;
        a10 += h1 * wv.x; a11 += h1 * wv.y; a12 += h1 * wv.z; a13 += h1 * wv.w;
    }
    __syncthreads();
    float* lg = shw;
    float4 bv = ((const float4*)b2)[tx];
    int c0 = tx * 4;
    int rowa = ty * 2, rowb = ty * 2 + 1;
    lg[rowa * 33 + c0 + 0] = a00 + bv.x;
    lg[rowa * 33 + c0 + 1] = a01 + bv.y;
    lg[rowa * 33 + c0 + 2] = a02 + bv.z;
    lg[rowa * 33 + c0 + 3] = a03 + bv.w;
    lg[rowb * 33 + c0 + 0] = a10 + bv.x;
    lg[rowb * 33 + c0 + 1] = a11 + bv.y;
    lg[rowb * 33 + c0 + 2] = a12 + bv.z;
    lg[rowb * 33 + c0 + 3] = a13 + bv.w;
    __syncthreads();

    int warp = tid >> 5, lane = tid & 31;
    #pragma unroll
    for (int r = 0; r < 8; r++) {
        int row = warp * 8 + r;
        float v = lg[row * 33 + lane];
        float mx = v;
        #pragma unroll
        for (int o = 16; o; o >>= 1) mx = fmaxf(mx, __shfl_xor_sync(~0u, mx, o));
        float ev = __expf(v - mx);
        float sum = ev;
        #pragma unroll
        for (int o = 16; o; o >>= 1) sum += __shfl_xor_sync(~0u, sum, o);
        float sv = ev / sum;
        int grow = r0 + row;
        g_sc[grow * KC + lane] = sv;
        dout[BG * KC * HID + 1 + grow * KC + lane] = sv;
    }
}

// ---------------- trace: 4 edges per warp-step, 8 lanes x float4 per row ----------------
__global__ __launch_bounds__(256) void traceK(const int* __restrict__ ei) {
    int tid = threadIdx.x, warp = tid >> 5, lane = tid & 31;
    int sub = lane >> 3, q = lane & 7;
    const float4* sc4 = (const float4*)g_sc;
    int base = blockIdx.x * 4096 + warp * 512;    // grid 128
    float part = 0.f;
    int gs = 0;
    #pragma unroll 2
    for (int j0 = 0; j0 < 512; j0 += 4) {
        int e = base + j0 + sub;
        int s = ei[e], d = ei[NE + e];
        gs = s;
        float4 a = sc4[s * 8 + q];
        float4 b = sc4[d * 8 + q];
        part += a.x * b.x + a.y * b.y + a.z * b.z + a.w * b.w;
    }
    #pragma unroll
    for (int o = 16; o; o >>= 1) part += __shfl_xor_sync(~0u, part, o);
    // per-warp graph attribution approximate at boundaries; exact for the loss (m uniform)
    if (lane == 0) atomicAdd(&g_trace[gs >> 11], part);
}

// ---------------- pooling: register-tiled s^T@xd, s^T@s, s^T@deg, colsum(s) ----------------
__global__ __launch_bounds__(256) void poolK() {
    __shared__ float shs[64 * 32];    // 8 KB
    __shared__ float shx[64 * 128];   // 32 KB
    __shared__ float shdeg[64];
    int tid = threadIdx.x;
    int b = blockIdx.x, ch = blockIdx.y;       // grid (16, 16)
    int tx = tid & 31, ty = tid >> 5;
    int sk = tid >> 3, sl = (tid & 7) * 4;
    float acc[4][4];
    #pragma unroll
    for (int c = 0; c < 4; c++)
        #pragma unroll
        for (int f = 0; f < 4; f++) acc[c][f] = 0.f;
    float ss0 = 0.f, ss1 = 0.f, ss2 = 0.f, ss3 = 0.f;
    float ca = 0.f, cs = 0.f;

    for (int sub = 0; sub < 2; sub++) {
        int n0 = b * NPG + ch * 128 + sub * 64;
        __syncthreads();
        {
            const float4* s4 = (const float4*)(g_sc + n0 * KC);
            float4* d4 = (float4*)shs;
            d4[tid] = s4[tid];
            d4[tid + 256] = s4[tid + 256];
        }
        {
            const float4* x4 = (const float4*)(g_xd + n0 * HID);
            float4* d4 = (float4*)shx;
            #pragma unroll
            for (int i2 = 0; i2 < 8; i2++) d4[tid + 256 * i2] = x4[tid + 256 * i2];
        }
        if (tid < 64) shdeg[tid] = g_odegf[n0 + tid];
        __syncthreads();

        #pragma unroll 4
        for (int n = 0; n < 64; n++) {
            float4 sv = *(const float4*)&shs[n * 32 + ty * 4];
            float4 xv = *(const float4*)&shx[n * 128 + tx * 4];
            acc[0][0] += sv.x * xv.x; acc[0][1] += sv.x * xv.y; acc[0][2] += sv.x * xv.z; acc[0][3] += sv.x * xv.w;
            acc[1][0] += sv.y * xv.x; acc[1][1] += sv.y * xv.y; acc[1][2] += sv.y * xv.z; acc[1][3] += sv.y * xv.w;
            acc[2][0] += sv.z * xv.x; acc[2][1] += sv.z * xv.y; acc[2][2] += sv.z * xv.z; acc[2][3] += sv.z * xv.w;
            acc[3][0] += sv.w * xv.x; acc[3][1] += sv.w * xv.y; acc[3][2] += sv.w * xv.z; acc[3][3] += sv.w * xv.w;
        }
        #pragma unroll 4
        for (int n = 0; n < 64; n++) {
            float a = shs[n * 32 + sk];
            float4 sb = *(const float4*)&shs[n * 32 + sl];
            ss0 += a * sb.x; ss1 += a * sb.y; ss2 += a * sb.z; ss3 += a * sb.w;
        }
        if (tid < 32) {
            for (int n = 0; n < 64; n++) {
                float sv = shs[n * 32 + tid];
                ca += sv * shdeg[n];
                cs += sv;
            }
        }
    }
    #pragma unroll
    for (int c = 0; c < 4; c++)
        #pragma unroll
        for (int f = 0; f < 4; f++)
            atomicAdd(&g_outacc[(b * KC + ty * 4 + c) * HID + tx * 4 + f], acc[c][f]);
    atomicAdd(&g_ssacc[b * KC * KC + sk * KC + sl + 0], ss0);
    atomicAdd(&g_ssacc[b * KC * KC + sk * KC + sl + 1], ss1);
    atomicAdd(&g_ssacc[b * KC * KC + sk * KC + sl + 2], ss2);
    atomicAdd(&g_ssacc[b * KC * KC + sk * KC + sl + 3], ss3);
    if (tid < 32) { atomicAdd(&g_caacc[b * KC + tid], ca); atomicAdd(&g_csacc[b * KC + tid], cs); }
}

// ---------------- out (selu + log_softmax) in blocks 0..511; loss in block 512 ----------------
__global__ __launch_bounds__(128) void outlossK(float* __restrict__ dout) {
    int tid = threadIdx.x;
    if (blockIdx.x < 512) {
        int row = blockIdx.x;
        float v = g_outacc[row * HID + tid];
        v = selu(v);
        __shared__ float red[128];
        red[tid] = v;
        __syncthreads();
        for (int s = 64; s; s >>= 1) {
            if (tid < s) red[tid] = fmaxf(red[tid], red[tid + s]);
            __syncthreads();
        }
        float mx = red[0];
        __syncthreads();
        red[tid] = __expf(v - mx);
        __syncthreads();
        for (int s = 64; s; s >>= 1) {
            if (tid < s) red[tid] += red[tid + s];
            __syncthreads();
        }
        dout[row * HID + tid] = v - mx - logf(red[0]);
        return;
    }
    // loss block: 4 warps, warp w handles graphs w, w+4, w+8, w+12
    __shared__ float shl[BG];
    int warp = tid >> 5, lane = tid & 31;
    for (int b = warp; b < BG; b += 4) {
        float ssq = 0.f, tr = 0.f;
        for (int p = lane; p < KC * KC; p += 32) {
            float v = g_ssacc[b * KC * KC + p];
            ssq += v * v;
            if ((p >> 5) == (p & 31)) tr += v;
        }
        float cav = g_caacc[b * KC + lane];
        float csv = g_csacc[b * KC + lane];
        float ca2 = cav * cav, cs2 = csv * csv;
        #pragma unroll
        for (int o = 16; o; o >>= 1) {
            ssq += __shfl_xor_sync(~0u, ssq, o);
            tr  += __shfl_xor_sync(~0u, tr, o);
            ca2 += __shfl_xor_sync(~0u, ca2, o);
            cs2 += __shfl_xor_sync(~0u, cs2, o);
        }
        if (lane == 0) {
            const float m = (float)(NPG * 16 / 2);   // N*DEG/2 per graph
            float spectral = -(g_trace[b] - ca2 / (2.f * m)) / (2.f * m);
            float fro = sqrtf(ssq);
            float ortho = sqrtf(fmaxf(2.f - 2.f * tr / (fro * SQRT_K), 0.f));
            float cluster = sqrtf(cs2) / (float)NPG * SQRT_K - 1.f;
            shl[b] = spectral + ortho + cluster;
        }
    }
    __syncthreads();
    if (tid == 0) {
        float t = 0.f;
        #pragma unroll
        for (int bb = 0; bb < BG; bb++) t += shl[bb];
        dout[BG * KC * HID] = t / (float)BG;
    }
}

// ---------------- launch ----------------
extern "C" void kernel_launch(void* const* d_in, const int* in_sizes, int n_in,
                              void* d_out, int out_size) {
    const float* x = nullptr;
    const int* ei = nullptr;
    const float *gw = nullptr, *gb = nullptr, *gms = nullptr;
    const float *w1 = nullptr, *b1 = nullptr, *w2 = nullptr, *b2 = nullptr;
    int n64 = 0;
    for (int i = 0; i < n_in; i++) {
        int sz = in_sizes[i];
        const void* p = d_in[i];
        if (sz == NTOT * CIN)      x  = (const float*)p;
        else if (sz == 2 * NE)     ei = (const int*)p;
        else if (sz == NTOT)       { /* batch: uniform, unused */ }
        else if (sz == CIN) {
            if (n64 == 0) gw = (const float*)p;
            else if (n64 == 1) gb = (const float*)p;
            else gms = (const float*)p;
            n64++;
        }
        else if (sz == CIN * HID)  w1 = (const float*)p;
        else if (sz == HID)        b1 = (const float*)p;
        else if (sz == HID * KC)   w2 = (const float*)p;
        else if (sz == KC)         b2 = (const float*)p;
    }
    float* dout = (float*)d_out;

    statsK<<<dim3(BG, 8), 256>>>(x);        // partial GN stats + zero all accumulators
    edgeK<<<NE / 256, 256>>>(ei);           // scalar: measured faster than int4
    setupK<<<NTOT / 256, 256>>>(gw, gb, gms);
    aggXK<<<NTOT / 8, 256>>>(x);            // gather raw x (64ch) + folded affine
    gemmK<<<NTOT / 64, 256>>>(w1, b1);      // agg @ w1 + b1, selu
    softmaxK<<<NTOT / 64, 256>>>(w2, b2, dout);
    traceK<<<NE / 4096, 256>>>(ei);
    poolK<<<dim3(BG, 16), 256>>>();
    outlossK<<<BG * KC + 1, 128>>>(dout);
}

// round 16
// speedup vs baseline: 1.3524x; 1.0700x over previous
#include <cuda_runtime.h>

// Problem constants
#define NTOT 32768      // total nodes (B*N)
#define BG   16         // graphs
#define NPG  2048       // nodes per graph
#define CIN  64
#define HID  128
#define KC   32
#define NE   524288     // edges
#define CAP  192        // per-node in-edge capacity

#define SELU_SCALE 1.0507009873554805f
#define SELU_ALPHA 1.6732632423543772f
#define SQRT_K     5.656854249492380f   // sqrt(32)

__device__ __forceinline__ float selu(float v) {
    return v > 0.f ? SELU_SCALE * v : SELU_SCALE * SELU_ALPHA * (__expf(v) - 1.f);
}

// ---------------- device scratch (zero-initialized at module load; outlossK re-zeros per run) ----------------
__device__ float g_ps1[BG * 8 * CIN];
__device__ float g_ps2[BG * 8 * CIN];
__device__ float g_na[BG * CIN];
__device__ float g_nb[BG * CIN];
__device__ float g_ah[NTOT * CIN];        // 8 MB  aggregated+normalized (pre-GEMM)
__device__ float g_xd[NTOT * HID];        // 16 MB post-GCN features
__device__ float g_sc[NTOT * KC];         // 4 MB  soft assignments
__device__ int   g_cnt[NTOT];
__device__ int   g_odeg[NTOT];
__device__ float g_dinv[NTOT];
__device__ float g_odegf[NTOT];
__device__ int   g_inlist[NTOT * CAP];    // 25 MB per-dst src lists
__device__ float g_outacc[BG * KC * HID];
__device__ float g_ssacc[BG * KC * KC];
__device__ float g_caacc[BG * KC];
__device__ float g_csacc[BG * KC];
__device__ float g_trace[BG];

// ---------------- fused: GN partial stats (blocks 0-127) || edge list build (blocks 128-2175) ----------------
// cnt/odeg were zeroed by the previous run's outlossK (zero-init on first run).
__global__ void statsedgeK(const float* __restrict__ x, const int* __restrict__ ei) {
    __shared__ float sh1[256], sh2[256];
    int tid = threadIdx.x;
    if (blockIdx.x >= 128) {
        int e = (blockIdx.x - 128) * 256 + tid;
        int s = ei[e];
        int d = ei[NE + e];
        int pos = atomicAdd(&g_cnt[d], 1);
        if (pos < CAP) g_inlist[d * CAP + pos] = s;
        atomicAdd(&g_odeg[s], 1);
        return;
    }
    int b = blockIdx.x >> 3, chunk = blockIdx.x & 7;
    int c = tid & 63, rsub = tid >> 6;
    int row0 = b * NPG + chunk * 256;
    float s1 = 0.f, s2 = 0.f;
    for (int r = rsub; r < 256; r += 4) {
        float v = x[(row0 + r) * CIN + c];
        s1 += v; s2 += v * v;
    }
    sh1[tid] = s1; sh2[tid] = s2;
    __syncthreads();
    if (rsub == 0) {
        s1 = sh1[c] + sh1[64 + c] + sh1[128 + c] + sh1[192 + c];
        s2 = sh2[c] + sh2[64 + c] + sh2[128 + c] + sh2[192 + c];
        g_ps1[(b * 8 + chunk) * CIN + c] = s1;
        g_ps2[(b * 8 + chunk) * CIN + c] = s2;
    }
}

// ---------------- setup: dinv/odegf per node + GN affine from partials ----------------
__global__ void setupK(const float* __restrict__ gw, const float* __restrict__ gb,
                       const float* __restrict__ gms) {
    int i = blockIdx.x * blockDim.x + threadIdx.x;   // 32768 threads
    g_dinv[i] = rsqrtf((float)(g_cnt[i] + 1));       // +1 self loop
    g_odegf[i] = (float)g_odeg[i];
    if (i < BG * CIN) {
        int b = i >> 6, c = i & 63;
        float s1 = 0.f, s2 = 0.f;
        #pragma unroll
        for (int ch = 0; ch < 8; ch++) {
            s1 += g_ps1[(b * 8 + ch) * CIN + c];
            s2 += g_ps2[(b * 8 + ch) * CIN + c];
        }
        float inv_n = 1.f / (float)NPG;
        float mean = s1 * inv_n;
        float ex2  = s2 * inv_n;
        float ms = gms[c];
        float var = ex2 - 2.f * ms * mean * mean + ms * ms * mean * mean;
        float rstd = rsqrtf(var + 1e-5f);
        float a = gw[c] * rstd;
        g_na[i] = a;
        g_nb[i] = gb[c] - a * ms * mean;
    }
}

// ---------------- GCN agg over raw x: half-warp per edge, float4 per lane (issue-optimized) ----------------
// A_hat(gn(x)) = a (.) A_hat(x) + (sum_w) * b
__global__ __launch_bounds__(256) void aggXK(const float* __restrict__ x) {
    __shared__ int   ssrc[8][CAP];
    __shared__ float swt[8][CAP];     // 12 KB
    int warp = threadIdx.x >> 5, lane = threadIdx.x & 31;
    int half = lane >> 4, chq = lane & 15;    // chq covers channels 4*chq..4*chq+3
    int i = blockIdx.x * 8 + warp;
    int cnt = g_cnt[i]; if (cnt > CAP) cnt = CAP;
    float di = g_dinv[i];
    for (int j = lane; j < cnt; j += 32) {
        int s = g_inlist[i * CAP + j];
        ssrc[warp][j] = s;
        swt[warp][j] = di * g_dinv[s];
    }
    __syncwarp();
    const float4* x4 = (const float4*)x;      // 16 float4 per row
    float ax, ay, az, aw, sumw;
    if (half == 0) {                          // self loop counted once (half 0)
        float4 self = x4[i * 16 + chq];
        float w0 = di * di;
        ax = w0 * self.x; ay = w0 * self.y; az = w0 * self.z; aw = w0 * self.w;
        sumw = w0;
    } else {
        ax = ay = az = aw = 0.f; sumw = 0.f;
    }
    // half h processes edges j = h, h+2, h+4, ... : one LDG.128 serves 2 edges/warp-instr
    for (int j = half; j < cnt; j += 2) {
        float wa = swt[warp][j];
        float4 v = x4[ssrc[warp][j] * 16 + chq];
        ax += wa * v.x; ay += wa * v.y; az += wa * v.z; aw += wa * v.w;
        sumw += wa;
    }
    ax += __shfl_xor_sync(~0u, ax, 16);
    ay += __shfl_xor_sync(~0u, ay, 16);
    az += __shfl_xor_sync(~0u, az, 16);
    aw += __shfl_xor_sync(~0u, aw, 16);
    sumw += __shfl_xor_sync(~0u, sumw, 16);
    if (half == 0) {
        int g = i >> 11;
        float4 av = ((const float4*)g_na)[g * 16 + chq];
        float4 bv = ((const float4*)g_nb)[g * 16 + chq];
        float4 r;
        r.x = av.x * ax + sumw * bv.x;
        r.y = av.y * ay + sumw * bv.y;
        r.z = av.z * az + sumw * bv.z;
        r.w = av.w * aw + sumw * bv.w;
        ((float4*)g_ah)[i * 16 + chq] = r;
    }
}

// ---------------- GEMM: g_ah[NT,64] @ w1[64,128] + b1, selu -> g_xd ----------------
__global__ __launch_bounds__(256) void gemmK(const float* __restrict__ w1,
                                             const float* __restrict__ b1) {
    __shared__ float shh[64][64];    // 16 KB
    __shared__ float shw[64][128];   // 32 KB
    int tid = threadIdx.x;
    int r0 = blockIdx.x * 64;

    int cl = tid & 63;
    #pragma unroll
    for (int i = 0; i < 16; i++) {
        int idx = tid + 256 * i;
        int r = idx >> 6;
        shh[r][cl] = g_ah[(r0 + r) * CIN + cl];
    }
    int cw = tid & 127;
    #pragma unroll
    for (int i = 0; i < 32; i++) {
        int idx = tid + 256 * i;
        int k = idx >> 7;
        shw[k][cw] = w1[idx];
    }
    __syncthreads();

    int tx = tid & 31, ty = tid >> 5;     // 8x4 register tile
    float acc[8][4];
    #pragma unroll
    for (int rr = 0; rr < 8; rr++)
        #pragma unroll
        for (int cc = 0; cc < 4; cc++) acc[rr][cc] = 0.f;

    #pragma unroll 4
    for (int k = 0; k < 64; k++) {
        float wv[4];
        #pragma unroll
        for (int cc = 0; cc < 4; cc++) wv[cc] = shw[k][tx + 32 * cc];
        #pragma unroll
        for (int rr = 0; rr < 8; rr++) {
            float hv = shh[ty + 8 * rr][k];
            #pragma unroll
            for (int cc = 0; cc < 4; cc++) acc[rr][cc] += hv * wv[cc];
        }
    }
    float bb[4];
    #pragma unroll
    for (int cc = 0; cc < 4; cc++) bb[cc] = b1[tx + 32 * cc];
    #pragma unroll
    for (int rr = 0; rr < 8; rr++) {
        int row = r0 + ty + 8 * rr;
        #pragma unroll
        for (int cc = 0; cc < 4; cc++)
            g_xd[row * HID + tx + 32 * cc] = selu(acc[rr][cc] + bb[cc]);
    }
}

// ---------------- s = softmax(xd @ w2 + b2): register-tiled GEMM + warp softmax ----------------
__global__ __launch_bounds__(256) void softmaxK(const float* __restrict__ w2,
                                                const float* __restrict__ b2,
                                                float* __restrict__ dout) {
    __shared__ float shx[128 * 64];   // k-major x tile  32 KB
    __shared__ float shw[128 * 32];   // w2 16 KB; reused for logits [64][33]
    int tid = threadIdx.x;
    int r0 = blockIdx.x * 64;         // grid 512

    {
        const float4* w4 = (const float4*)w2;
        float4* s4 = (float4*)shw;
        #pragma unroll
        for (int i = 0; i < 4; i++) s4[tid + 256 * i] = w4[tid + 256 * i];
    }
    {
        int row = tid >> 2, kq = tid & 3;
        const float4* xd4 = (const float4*)g_xd;
        #pragma unroll
        for (int it = 0; it < 8; it++) {
            float4 v = xd4[(r0 + row) * 32 + kq * 8 + it];
            int k = kq * 32 + it * 4;
            shx[(k + 0) * 64 + row] = v.x;
            shx[(k + 1) * 64 + row] = v.y;
            shx[(k + 2) * 64 + row] = v.z;
            shx[(k + 3) * 64 + row] = v.w;
        }
    }
    __syncthreads();

    int tx = tid & 7, ty = tid >> 3;
    float a00=0.f,a01=0.f,a02=0.f,a03=0.f,a10=0.f,a11=0.f,a12=0.f,a13=0.f;
    #pragma unroll 8
    for (int k = 0; k < 128; k++) {
        float4 wv = *(const float4*)&shw[k * 32 + tx * 4];
        float h0 = shx[k * 64 + ty * 2];
        float h1 = shx[k * 64 + ty * 2 + 1];
        a00 += h0 * wv.x; a01 += h0 * wv.y; a02 += h0 * wv.z; a03 += h0 * wv.w;
        a10 += h1 * wv.x; a11 += h1 * wv.y; a12 += h1 * wv.z; a13 += h1 * wv.w;
    }
    __syncthreads();
    float* lg = shw;
    float4 bv = ((const float4*)b2)[tx];
    int c0 = tx * 4;
    int rowa = ty * 2, rowb = ty * 2 + 1;
    lg[rowa * 33 + c0 + 0] = a00 + bv.x;
    lg[rowa * 33 + c0 + 1] = a01 + bv.y;
    lg[rowa * 33 + c0 + 2] = a02 + bv.z;
    lg[rowa * 33 + c0 + 3] = a03 + bv.w;
    lg[rowb * 33 + c0 + 0] = a10 + bv.x;
    lg[rowb * 33 + c0 + 1] = a11 + bv.y;
    lg[rowb * 33 + c0 + 2] = a12 + bv.z;
    lg[rowb * 33 + c0 + 3] = a13 + bv.w;
    __syncthreads();

    int warp = tid >> 5, lane = tid & 31;
    #pragma unroll
    for (int r = 0; r < 8; r++) {
        int row = warp * 8 + r;
        float v = lg[row * 33 + lane];
        float mx = v;
        #pragma unroll
        for (int o = 16; o; o >>= 1) mx = fmaxf(mx, __shfl_xor_sync(~0u, mx, o));
        float ev = __expf(v - mx);
        float sum = ev;
        #pragma unroll
        for (int o = 16; o; o >>= 1) sum += __shfl_xor_sync(~0u, sum, o);
        float sv = ev / sum;
        int grow = r0 + row;
        g_sc[grow * KC + lane] = sv;
        dout[BG * KC * HID + 1 + grow * KC + lane] = sv;
    }
}

// ---------------- fused: trace (blocks 0-127) || pooling (blocks 128-383) ----------------
__global__ __launch_bounds__(256) void tracepoolK(const int* __restrict__ ei) {
    __shared__ float shs[64 * 32];    // 8 KB
    __shared__ float shx[64 * 128];   // 32 KB
    __shared__ float shdeg[64];
    int tid = threadIdx.x;

    if (blockIdx.x < 128) {
        // trace: sum over edges of dot(s[src], s[dst])
        int warp = tid >> 5, lane = tid & 31;
        int sub = lane >> 3, q = lane & 7;
        const float4* sc4 = (const float4*)g_sc;
        int base = blockIdx.x * 4096 + warp * 512;
        float part = 0.f;
        int gs = 0;
        #pragma unroll 2
        for (int j0 = 0; j0 < 512; j0 += 4) {
            int e = base + j0 + sub;
            int s = ei[e], d = ei[NE + e];
            gs = s;
            float4 a = sc4[s * 8 + q];
            float4 b = sc4[d * 8 + q];
            part += a.x * b.x + a.y * b.y + a.z * b.z + a.w * b.w;
        }
        #pragma unroll
        for (int o = 16; o; o >>= 1) part += __shfl_xor_sync(~0u, part, o);
        // per-warp graph attribution approximate at boundaries; exact for loss (m uniform)
        if (lane == 0) atomicAdd(&g_trace[gs >> 11], part);
        return;
    }

    int bb = blockIdx.x - 128;
    int b = bb >> 4, ch = bb & 15;
    int tx = tid & 31, ty = tid >> 5;
    int sk = tid >> 3, sl = (tid & 7) * 4;
    float acc[4][4];
    #pragma unroll
    for (int c = 0; c < 4; c++)
        #pragma unroll
        for (int f = 0; f < 4; f++) acc[c][f] = 0.f;
    float ss0 = 0.f, ss1 = 0.f, ss2 = 0.f, ss3 = 0.f;
    float ca = 0.f, cs = 0.f;

    for (int sub = 0; sub < 2; sub++) {
        int n0 = b * NPG + ch * 128 + sub * 64;
        __syncthreads();
        {
            const float4* s4 = (const float4*)(g_sc + n0 * KC);
            float4* d4 = (float4*)shs;
            d4[tid] = s4[tid];
            d4[tid + 256] = s4[tid + 256];
        }
        {
            const float4* x4 = (const float4*)(g_xd + n0 * HID);
            float4* d4 = (float4*)shx;
            #pragma unroll
            for (int i2 = 0; i2 < 8; i2++) d4[tid + 256 * i2] = x4[tid + 256 * i2];
        }
        if (tid < 64) shdeg[tid] = g_odegf[n0 + tid];
        __syncthreads();

        #pragma unroll 4
        for (int n = 0; n < 64; n++) {
            float4 sv = *(const float4*)&shs[n * 32 + ty * 4];
            float4 xv = *(const float4*)&shx[n * 128 + tx * 4];
            acc[0][0] += sv.x * xv.x; acc[0][1] += sv.x * xv.y; acc[0][2] += sv.x * xv.z; acc[0][3] += sv.x * xv.w;
            acc[1][0] += sv.y * xv.x; acc[1][1] += sv.y * xv.y; acc[1][2] += sv.y * xv.z; acc[1][3] += sv.y * xv.w;
            acc[2][0] += sv.z * xv.x; acc[2][1] += sv.z * xv.y; acc[2][2] += sv.z * xv.z; acc[2][3] += sv.z * xv.w;
            acc[3][0] += sv.w * xv.x; acc[3][1] += sv.w * xv.y; acc[3][2] += sv.w * xv.z; acc[3][3] += sv.w * xv.w;
        }
        #pragma unroll 4
        for (int n = 0; n < 64; n++) {
            float a = shs[n * 32 + sk];
            float4 sb = *(const float4*)&shs[n * 32 + sl];
            ss0 += a * sb.x; ss1 += a * sb.y; ss2 += a * sb.z; ss3 += a * sb.w;
        }
        if (tid < 32) {
            for (int n = 0; n < 64; n++) {
                float sv = shs[n * 32 + tid];
                ca += sv * shdeg[n];
                cs += sv;
            }
        }
    }
    #pragma unroll
    for (int c = 0; c < 4; c++)
        #pragma unroll
        for (int f = 0; f < 4; f++)
            atomicAdd(&g_outacc[(b * KC + ty * 4 + c) * HID + tx * 4 + f], acc[c][f]);
    atomicAdd(&g_ssacc[b * KC * KC + sk * KC + sl + 0], ss0);
    atomicAdd(&g_ssacc[b * KC * KC + sk * KC + sl + 1], ss1);
    atomicAdd(&g_ssacc[b * KC * KC + sk * KC + sl + 2], ss2);
    atomicAdd(&g_ssacc[b * KC * KC + sk * KC + sl + 3], ss3);
    if (tid < 32) { atomicAdd(&g_caacc[b * KC + tid], ca); atomicAdd(&g_csacc[b * KC + tid], cs); }
}

// ---------------- out + loss + re-zero state for the next run ----------------
__global__ __launch_bounds__(128) void outlossK(float* __restrict__ dout) {
    int tid = threadIdx.x;
    int t = blockIdx.x * 128 + tid;
    if (t < NTOT) { g_cnt[t] = 0; g_odeg[t] = 0; }   // reset for next run (zero-init covers run 1)
    if (blockIdx.x < 512) {
        int row = blockIdx.x;
        float v = g_outacc[row * HID + tid];
        g_outacc[row * HID + tid] = 0.f;             // re-zero after read
        v = selu(v);
        __shared__ float red[128];
        red[tid] = v;
        __syncthreads();
        for (int s = 64; s; s >>= 1) {
            if (tid < s) red[tid] = fmaxf(red[tid], red[tid + s]);
            __syncthreads();
        }
        float mx = red[0];
        __syncthreads();
        red[tid] = __expf(v - mx);
        __syncthreads();
        for (int s = 64; s; s >>= 1) {
            if (tid < s) red[tid] += red[tid + s];
            __syncthreads();
        }
        dout[row * HID + tid] = v - mx - logf(red[0]);
        return;
    }
    // loss block (512): 4 warps, warp w handles graphs w, w+4, w+8, w+12
    __shared__ float shl[BG];
    int warp = tid >> 5, lane = tid & 31;
    for (int b = warp; b < BG; b += 4) {
        float ssq = 0.f, tr = 0.f;
        for (int p = lane; p < KC * KC; p += 32) {
            float v = g_ssacc[b * KC * KC + p];
            ssq += v * v;
            if ((p >> 5) == (p & 31)) tr += v;
        }
        float cav = g_caacc[b * KC + lane];
        float csv = g_csacc[b * KC + lane];
        float ca2 = cav * cav, cs2 = csv * csv;
        #pragma unroll
        for (int o = 16; o; o >>= 1) {
            ssq += __shfl_xor_sync(~0u, ssq, o);
            tr  += __shfl_xor_sync(~0u, tr, o);
            ca2 += __shfl_xor_sync(~0u, ca2, o);
            cs2 += __shfl_xor_sync(~0u, cs2, o);
        }
        if (lane == 0) {
            const float m = (float)(NPG * 16 / 2);   // N*DEG/2 per graph
            float spectral = -(g_trace[b] - ca2 / (2.f * m)) / (2.f * m);
            float fro = sqrtf(ssq);
            float ortho = sqrtf(fmaxf(2.f - 2.f * tr / (fro * SQRT_K), 0.f));
            float cluster = sqrtf(cs2) / (float)NPG * SQRT_K - 1.f;
            shl[b] = spectral + ortho + cluster;
        }
    }
    __syncthreads();                                  // all reads done
    for (int p = tid; p < BG * KC * KC; p += 128) g_ssacc[p] = 0.f;
    for (int p = tid; p < BG * KC; p += 128) { g_caacc[p] = 0.f; g_csacc[p] = 0.f; }
    if (tid < BG) g_trace[tid] = 0.f;
    if (tid == 0) {
        float tt = 0.f;
        #pragma unroll
        for (int bb = 0; bb < BG; bb++) tt += shl[bb];
        dout[BG * KC * HID] = tt / (float)BG;
    }
}

// ---------------- launch (7 kernels) ----------------
extern "C" void kernel_launch(void* const* d_in, const int* in_sizes, int n_in,
                              void* d_out, int out_size) {
    const float* x = nullptr;
    const int* ei = nullptr;
    const float *gw = nullptr, *gb = nullptr, *gms = nullptr;
    const float *w1 = nullptr, *b1 = nullptr, *w2 = nullptr, *b2 = nullptr;
    int n64 = 0;
    for (int i = 0; i < n_in; i++) {
        int sz = in_sizes[i];
        const void* p = d_in[i];
        if (sz == NTOT * CIN)      x  = (const float*)p;
        else if (sz == 2 * NE)     ei = (const int*)p;
        else if (sz == NTOT)       { /* batch: uniform, unused */ }
        else if (sz == CIN) {
            if (n64 == 0) gw = (const float*)p;
            else if (n64 == 1) gb = (const float*)p;
            else gms = (const float*)p;
            n64++;
        }
        else if (sz == CIN * HID)  w1 = (const float*)p;
        else if (sz == HID)        b1 = (const float*)p;
        else if (sz == HID * KC)   w2 = (const float*)p;
        else if (sz == KC)         b2 = (const float*)p;
    }
    float* dout = (float*)d_out;

    statsedgeK<<<128 + NE / 256, 256>>>(x, ei);   // stats blocks || edge blocks (overlap)
    setupK<<<NTOT / 256, 256>>>(gw, gb, gms);
    aggXK<<<NTOT / 8, 256>>>(x);                  // half-warp-per-edge float4 gather
    gemmK<<<NTOT / 64, 256>>>(w1, b1);
    softmaxK<<<NTOT / 64, 256>>>(w2, b2, dout);
    tracepoolK<<<128 + BG * 16, 256>>>(ei);       // trace blocks || pool blocks
    outlossK<<<BG * KC + 1, 128>>>(dout);
}

// round 17
// speedup vs baseline: 1.3987x; 1.0342x over previous
#include <cuda_runtime.h>
#include <cstdint>

// Problem constants
#define NTOT 32768      // total nodes (B*N)
#define BG   16         // graphs
#define NPG  2048       // nodes per graph
#define CIN  64
#define HID  128
#define KC   32
#define NE   524288     // edges
#define CAP  192        // per-node in-edge capacity

#define SELU_SCALE 1.0507009873554805f
#define SELU_ALPHA 1.6732632423543772f
#define SQRT_K     5.656854249492380f   // sqrt(32)

__device__ __forceinline__ float selu(float v) {
    return v > 0.f ? SELU_SCALE * v : SELU_SCALE * SELU_ALPHA * (__expf(v) - 1.f);
}

// ---------------- device scratch (zero-initialized at load; outlossK re-zeros per run) ----------------
__device__ float g_ps1[BG * 8 * CIN];
__device__ float g_ps2[BG * 8 * CIN];
__device__ float g_na[BG * CIN];
__device__ float g_nb[BG * CIN];
__device__ float g_ah[NTOT * CIN];        // 8 MB  aggregated+normalized (pre-GEMM)
__device__ float g_xd[NTOT * HID];        // 16 MB post-GCN features
__device__ float g_sc[NTOT * KC];         // 4 MB  soft assignments
__device__ int   g_cnt[NTOT];
__device__ int   g_odeg[NTOT];
__device__ float g_dinv[NTOT];
__device__ float g_odegf[NTOT];
__device__ int   g_inlist[NTOT * CAP];    // 25 MB per-dst src lists
__device__ float g_outacc[BG * KC * HID];
__device__ float g_ssacc[BG * KC * KC];
__device__ float g_caacc[BG * KC];
__device__ float g_csacc[BG * KC];
__device__ float g_trace[BG];

// ---------------- fused: GN partial stats (blocks 0-127) || edge list build (blocks 128-2175) ----------------
__global__ void statsedgeK(const float* __restrict__ x, const int* __restrict__ ei) {
    __shared__ float sh1[256], sh2[256];
    int tid = threadIdx.x;
    if (blockIdx.x >= 128) {
        int e = (blockIdx.x - 128) * 256 + tid;
        int s = ei[e];
        int d = ei[NE + e];
        int pos = atomicAdd(&g_cnt[d], 1);
        if (pos < CAP) g_inlist[d * CAP + pos] = s;
        atomicAdd(&g_odeg[s], 1);
        return;
    }
    int b = blockIdx.x >> 3, chunk = blockIdx.x & 7;
    int c = tid & 63, rsub = tid >> 6;
    int row0 = b * NPG + chunk * 256;
    float s1 = 0.f, s2 = 0.f;
    for (int r = rsub; r < 256; r += 4) {
        float v = x[(row0 + r) * CIN + c];
        s1 += v; s2 += v * v;
    }
    sh1[tid] = s1; sh2[tid] = s2;
    __syncthreads();
    if (rsub == 0) {
        s1 = sh1[c] + sh1[64 + c] + sh1[128 + c] + sh1[192 + c];
        s2 = sh2[c] + sh2[64 + c] + sh2[128 + c] + sh2[192 + c];
        g_ps1[(b * 8 + chunk) * CIN + c] = s1;
        g_ps2[(b * 8 + chunk) * CIN + c] = s2;
    }
}

// ---------------- setup: dinv/odegf per node + GN affine from partials ----------------
__global__ void setupK(const float* __restrict__ gw, const float* __restrict__ gb,
                       const float* __restrict__ gms) {
    int i = blockIdx.x * blockDim.x + threadIdx.x;   // 32768 threads
    g_dinv[i] = rsqrtf((float)(g_cnt[i] + 1));       // +1 self loop
    g_odegf[i] = (float)g_odeg[i];
    if (i < BG * CIN) {
        int b = i >> 6, c = i & 63;
        float s1 = 0.f, s2 = 0.f;
        #pragma unroll
        for (int ch = 0; ch < 8; ch++) {
            s1 += g_ps1[(b * 8 + ch) * CIN + c];
            s2 += g_ps2[(b * 8 + ch) * CIN + c];
        }
        float inv_n = 1.f / (float)NPG;
        float mean = s1 * inv_n;
        float ex2  = s2 * inv_n;
        float ms = gms[c];
        float var = ex2 - 2.f * ms * mean * mean + ms * ms * mean * mean;
        float rstd = rsqrtf(var + 1e-5f);
        float a = gw[c] * rstd;
        g_na[i] = a;
        g_nb[i] = gb[c] - a * ms * mean;
    }
}

// ---------------- GCN agg over raw x: half-warp per edge, float4 per lane ----------------
__global__ __launch_bounds__(256) void aggXK(const float* __restrict__ x) {
    __shared__ int   ssrc[8][CAP];
    __shared__ float swt[8][CAP];     // 12 KB
    int warp = threadIdx.x >> 5, lane = threadIdx.x & 31;
    int half = lane >> 4, chq = lane & 15;
    int i = blockIdx.x * 8 + warp;
    int cnt = g_cnt[i]; if (cnt > CAP) cnt = CAP;
    float di = g_dinv[i];
    for (int j = lane; j < cnt; j += 32) {
        int s = g_inlist[i * CAP + j];
        ssrc[warp][j] = s;
        swt[warp][j] = di * g_dinv[s];
    }
    __syncwarp();
    const float4* x4 = (const float4*)x;
    float ax, ay, az, aw, sumw;
    if (half == 0) {
        float4 self = x4[i * 16 + chq];
        float w0 = di * di;
        ax = w0 * self.x; ay = w0 * self.y; az = w0 * self.z; aw = w0 * self.w;
        sumw = w0;
    } else {
        ax = ay = az = aw = 0.f; sumw = 0.f;
    }
    for (int j = half; j < cnt; j += 2) {
        float wa = swt[warp][j];
        float4 v = x4[ssrc[warp][j] * 16 + chq];
        ax += wa * v.x; ay += wa * v.y; az += wa * v.z; aw += wa * v.w;
        sumw += wa;
    }
    ax += __shfl_xor_sync(~0u, ax, 16);
    ay += __shfl_xor_sync(~0u, ay, 16);
    az += __shfl_xor_sync(~0u, az, 16);
    aw += __shfl_xor_sync(~0u, aw, 16);
    sumw += __shfl_xor_sync(~0u, sumw, 16);
    if (half == 0) {
        int g = i >> 11;
        float4 av = ((const float4*)g_na)[g * 16 + chq];
        float4 bv = ((const float4*)g_nb)[g * 16 + chq];
        float4 r;
        r.x = av.x * ax + sumw * bv.x;
        r.y = av.y * ay + sumw * bv.y;
        r.z = av.z * az + sumw * bv.z;
        r.w = av.w * aw + sumw * bv.w;
        ((float4*)g_ah)[i * 16 + chq] = r;
    }
}

// ---------------- GEMM via packed f32x2 FMA: g_ah[NT,64] @ w1[64,128] + b1, selu -> g_xd ----------------
// Thread tile: 8 rows x 4 CONTIGUOUS cols. w operand = 1 LDS.128 (two aligned b64 halves),
// h operand = warp-broadcast LDS.32 + mov.b64 {h,h}. 16 FFMA2 replace 32 FFMA per thread-k.
__global__ __launch_bounds__(256) void gemmK(const float* __restrict__ w1,
                                             const float* __restrict__ b1) {
    __shared__ float shh[64][64];    // [row][k]  16 KB
    __shared__ float shw[64][128];   // [k][col]  32 KB (48 KB total)
    int tid = threadIdx.x;
    int r0 = blockIdx.x * 64;

    int cl = tid & 63;
    #pragma unroll
    for (int i = 0; i < 16; i++) {
        int idx = tid + 256 * i;
        int r = idx >> 6;
        shh[r][cl] = g_ah[(r0 + r) * CIN + cl];
    }
    int cw = tid & 127;
    #pragma unroll
    for (int i = 0; i < 32; i++) {
        int idx = tid + 256 * i;
        int k = idx >> 7;
        shw[k][cw] = w1[idx];
    }
    __syncthreads();

    int tx = tid & 31, ty = tid >> 5;     // cols tx*4..tx*4+3 (contiguous), rows ty+8*rr
    uint64_t acc[8][2];
    #pragma unroll
    for (int rr = 0; rr < 8; rr++) { acc[rr][0] = 0ull; acc[rr][1] = 0ull; }  // {0.f,0.f}

    #pragma unroll 4
    for (int k = 0; k < 64; k++) {
        // one LDS.128: 4 contiguous w columns as two aligned f32x2 pairs
        ulonglong2 wp = *(const ulonglong2*)&shw[k][tx * 4];
        #pragma unroll
        for (int rr = 0; rr < 8; rr++) {
            float h = shh[ty + 8 * rr][k];           // warp-broadcast
            uint64_t h2;
            asm("mov.b64 %0, {%1, %1};" : "=l"(h2) : "f"(h));
            asm("fma.rn.f32x2 %0, %1, %2, %0;" : "+l"(acc[rr][0]) : "l"(h2), "l"(wp.x));
            asm("fma.rn.f32x2 %0, %1, %2, %0;" : "+l"(acc[rr][1]) : "l"(h2), "l"(wp.y));
        }
    }

    float4 bb = *(const float4*)&b1[tx * 4];
    #pragma unroll
    for (int rr = 0; rr < 8; rr++) {
        int row = r0 + ty + 8 * rr;
        float a0, a1, a2, a3;
        asm("mov.b64 {%0, %1}, %2;" : "=f"(a0), "=f"(a1) : "l"(acc[rr][0]));
        asm("mov.b64 {%0, %1}, %2;" : "=f"(a2), "=f"(a3) : "l"(acc[rr][1]));
        float4 r;
        r.x = selu(a0 + bb.x);
        r.y = selu(a1 + bb.y);
        r.z = selu(a2 + bb.z);
        r.w = selu(a3 + bb.w);
        *(float4*)&g_xd[row * HID + tx * 4] = r;
    }
}

// ---------------- s = softmax(xd @ w2 + b2): register-tiled GEMM + warp softmax ----------------
__global__ __launch_bounds__(256) void softmaxK(const float* __restrict__ w2,
                                                const float* __restrict__ b2,
                                                float* __restrict__ dout) {
    __shared__ float shx[128 * 64];   // k-major x tile  32 KB
    __shared__ float shw[128 * 32];   // w2 16 KB; reused for logits [64][33]
    int tid = threadIdx.x;
    int r0 = blockIdx.x * 64;         // grid 512

    {
        const float4* w4 = (const float4*)w2;
        float4* s4 = (float4*)shw;
        #pragma unroll
        for (int i = 0; i < 4; i++) s4[tid + 256 * i] = w4[tid + 256 * i];
    }
    {
        int row = tid >> 2, kq = tid & 3;
        const float4* xd4 = (const float4*)g_xd;
        #pragma unroll
        for (int it = 0; it < 8; it++) {
            float4 v = xd4[(r0 + row) * 32 + kq * 8 + it];
            int k = kq * 32 + it * 4;
            shx[(k + 0) * 64 + row] = v.x;
            shx[(k + 1) * 64 + row] = v.y;
            shx[(k + 2) * 64 + row] = v.z;
            shx[(k + 3) * 64 + row] = v.w;
        }
    }
    __syncthreads();

    int tx = tid & 7, ty = tid >> 3;
    float a00=0.f,a01=0.f,a02=0.f,a03=0.f,a10=0.f,a11=0.f,a12=0.f,a13=0.f;
    #pragma unroll 8
    for (int k = 0; k < 128; k++) {
        float4 wv = *(const float4*)&shw[k * 32 + tx * 4];
        float h0 = shx[k * 64 + ty * 2];
        float h1 = shx[k * 64 + ty * 2 + 1];
        a00 += h0 * wv.x; a01 += h0 * wv.y; a02 += h0 * wv.z; a03 += h0 * wv.w;
        a10 += h1 * wv.x; a11 += h1 * wv.y; a12 += h1 * wv.z; a13 += h1 * wv.w;
    }
    __syncthreads();
    float* lg = shw;
    float4 bv = ((const float4*)b2)[tx];
    int c0 = tx * 4;
    int rowa = ty * 2, rowb = ty * 2 + 1;
    lg[rowa * 33 + c0 + 0] = a00 + bv.x;
    lg[rowa * 33 + c0 + 1] = a01 + bv.y;
    lg[rowa * 33 + c0 + 2] = a02 + bv.z;
    lg[rowa * 33 + c0 + 3] = a03 + bv.w;
    lg[rowb * 33 + c0 + 0] = a10 + bv.x;
    lg[rowb * 33 + c0 + 1] = a11 + bv.y;
    lg[rowb * 33 + c0 + 2] = a12 + bv.z;
    lg[rowb * 33 + c0 + 3] = a13 + bv.w;
    __syncthreads();

    int warp = tid >> 5, lane = tid & 31;
    #pragma unroll
    for (int r = 0; r < 8; r++) {
        int row = warp * 8 + r;
        float v = lg[row * 33 + lane];
        float mx = v;
        #pragma unroll
        for (int o = 16; o; o >>= 1) mx = fmaxf(mx, __shfl_xor_sync(~0u, mx, o));
        float ev = __expf(v - mx);
        float sum = ev;
        #pragma unroll
        for (int o = 16; o; o >>= 1) sum += __shfl_xor_sync(~0u, sum, o);
        float sv = ev / sum;
        int grow = r0 + row;
        g_sc[grow * KC + lane] = sv;
        dout[BG * KC * HID + 1 + grow * KC + lane] = sv;
    }
}

// ---------------- fused: trace (blocks 0-127) || pooling (blocks 128-383) ----------------
__global__ __launch_bounds__(256) void tracepoolK(const int* __restrict__ ei) {
    __shared__ float shs[64 * 32];    // 8 KB
    __shared__ float shx[64 * 128];   // 32 KB
    __shared__ float shdeg[64];
    int tid = threadIdx.x;

    if (blockIdx.x < 128) {
        int warp = tid >> 5, lane = tid & 31;
        int sub = lane >> 3, q = lane & 7;
        const float4* sc4 = (const float4*)g_sc;
        int base = blockIdx.x * 4096 + warp * 512;
        float part = 0.f;
        int gs = 0;
        #pragma unroll 2
        for (int j0 = 0; j0 < 512; j0 += 4) {
            int e = base + j0 + sub;
            int s = ei[e], d = ei[NE + e];
            gs = s;
            float4 a = sc4[s * 8 + q];
            float4 b = sc4[d * 8 + q];
            part += a.x * b.x + a.y * b.y + a.z * b.z + a.w * b.w;
        }
        #pragma unroll
        for (int o = 16; o; o >>= 1) part += __shfl_xor_sync(~0u, part, o);
        if (lane == 0) atomicAdd(&g_trace[gs >> 11], part);
        return;
    }

    int bb = blockIdx.x - 128;
    int b = bb >> 4, ch = bb & 15;
    int tx = tid & 31, ty = tid >> 5;
    int sk = tid >> 3, sl = (tid & 7) * 4;
    float acc[4][4];
    #pragma unroll
    for (int c = 0; c < 4; c++)
        #pragma unroll
        for (int f = 0; f < 4; f++) acc[c][f] = 0.f;
    float ss0 = 0.f, ss1 = 0.f, ss2 = 0.f, ss3 = 0.f;
    float ca = 0.f, cs = 0.f;

    for (int sub = 0; sub < 2; sub++) {
        int n0 = b * NPG + ch * 128 + sub * 64;
        __syncthreads();
        {
            const float4* s4 = (const float4*)(g_sc + n0 * KC);
            float4* d4 = (float4*)shs;
            d4[tid] = s4[tid];
            d4[tid + 256] = s4[tid + 256];
        }
        {
            const float4* x4 = (const float4*)(g_xd + n0 * HID);
            float4* d4 = (float4*)shx;
            #pragma unroll
            for (int i2 = 0; i2 < 8; i2++) d4[tid + 256 * i2] = x4[tid + 256 * i2];
        }
        if (tid < 64) shdeg[tid] = g_odegf[n0 + tid];
        __syncthreads();

        #pragma unroll 4
        for (int n = 0; n < 64; n++) {
            float4 sv = *(const float4*)&shs[n * 32 + ty * 4];
            float4 xv = *(const float4*)&shx[n * 128 + tx * 4];
            acc[0][0] += sv.x * xv.x; acc[0][1] += sv.x * xv.y; acc[0][2] += sv.x * xv.z; acc[0][3] += sv.x * xv.w;
            acc[1][0] += sv.y * xv.x; acc[1][1] += sv.y * xv.y; acc[1][2] += sv.y * xv.z; acc[1][3] += sv.y * xv.w;
            acc[2][0] += sv.z * xv.x; acc[2][1] += sv.z * xv.y; acc[2][2] += sv.z * xv.z; acc[2][3] += sv.z * xv.w;
            acc[3][0] += sv.w * xv.x; acc[3][1] += sv.w * xv.y; acc[3][2] += sv.w * xv.z; acc[3][3] += sv.w * xv.w;
        }
        #pragma unroll 4
        for (int n = 0; n < 64; n++) {
            float a = shs[n * 32 + sk];
            float4 sb = *(const float4*)&shs[n * 32 + sl];
            ss0 += a * sb.x; ss1 += a * sb.y; ss2 += a * sb.z; ss3 += a * sb.w;
        }
        if (tid < 32) {
            for (int n = 0; n < 64; n++) {
                float sv = shs[n * 32 + tid];
                ca += sv * shdeg[n];
                cs += sv;
            }
        }
    }
    #pragma unroll
    for (int c = 0; c < 4; c++)
        #pragma unroll
        for (int f = 0; f < 4; f++)
            atomicAdd(&g_outacc[(b * KC + ty * 4 + c) * HID + tx * 4 + f], acc[c][f]);
    atomicAdd(&g_ssacc[b * KC * KC + sk * KC + sl + 0], ss0);
    atomicAdd(&g_ssacc[b * KC * KC + sk * KC + sl + 1], ss1);
    atomicAdd(&g_ssacc[b * KC * KC + sk * KC + sl + 2], ss2);
    atomicAdd(&g_ssacc[b * KC * KC + sk * KC + sl + 3], ss3);
    if (tid < 32) { atomicAdd(&g_caacc[b * KC + tid], ca); atomicAdd(&g_csacc[b * KC + tid], cs); }
}

// ---------------- out + loss + re-zero state for the next run ----------------
__global__ __launch_bounds__(128) void outlossK(float* __restrict__ dout) {
    int tid = threadIdx.x;
    int t = blockIdx.x * 128 + tid;
    if (t < NTOT) { g_cnt[t] = 0; g_odeg[t] = 0; }   // reset for next run (zero-init run 1)
    if (blockIdx.x < 512) {
        int row = blockIdx.x;
        float v = g_outacc[row * HID + tid];
        g_outacc[row * HID + tid] = 0.f;
        v = selu(v);
        __shared__ float red[128];
        red[tid] = v;
        __syncthreads();
        for (int s = 64; s; s >>= 1) {
            if (tid < s) red[tid] = fmaxf(red[tid], red[tid + s]);
            __syncthreads();
        }
        float mx = red[0];
        __syncthreads();
        red[tid] = __expf(v - mx);
        __syncthreads();
        for (int s = 64; s; s >>= 1) {
            if (tid < s) red[tid] += red[tid + s];
            __syncthreads();
        }
        dout[row * HID + tid] = v - mx - logf(red[0]);
        return;
    }
    __shared__ float shl[BG];
    int warp = tid >> 5, lane = tid & 31;
    for (int b = warp; b < BG; b += 4) {
        float ssq = 0.f, tr = 0.f;
        for (int p = lane; p < KC * KC; p += 32) {
            float v = g_ssacc[b * KC * KC + p];
            ssq += v * v;
            if ((p >> 5) == (p & 31)) tr += v;
        }
        float cav = g_caacc[b * KC + lane];
        float csv = g_csacc[b * KC + lane];
        float ca2 = cav * cav, cs2 = csv * csv;
        #pragma unroll
        for (int o = 16; o; o >>= 1) {
            ssq += __shfl_xor_sync(~0u, ssq, o);
            tr  += __shfl_xor_sync(~0u, tr, o);
            ca2 += __shfl_xor_sync(~0u, ca2, o);
            cs2 += __shfl_xor_sync(~0u, cs2, o);
        }
        if (lane == 0) {
            const float m = (float)(NPG * 16 / 2);
            float spectral = -(g_trace[b] - ca2 / (2.f * m)) / (2.f * m);
            float fro = sqrtf(ssq);
            float ortho = sqrtf(fmaxf(2.f - 2.f * tr / (fro * SQRT_K), 0.f));
            float cluster = sqrtf(cs2) / (float)NPG * SQRT_K - 1.f;
            shl[b] = spectral + ortho + cluster;
        }
    }
    __syncthreads();
    for (int p = tid; p < BG * KC * KC; p += 128) g_ssacc[p] = 0.f;
    for (int p = tid; p < BG * KC; p += 128) { g_caacc[p] = 0.f; g_csacc[p] = 0.f; }
    if (tid < BG) g_trace[tid] = 0.f;
    if (tid == 0) {
        float tt = 0.f;
        #pragma unroll
        for (int bb = 0; bb < BG; bb++) tt += shl[bb];
        dout[BG * KC * HID] = tt / (float)BG;
    }
}

// ---------------- launch (7 kernels) ----------------
extern "C" void kernel_launch(void* const* d_in, const int* in_sizes, int n_in,
                              void* d_out, int out_size) {
    const float* x = nullptr;
    const int* ei = nullptr;
    const float *gw = nullptr, *gb = nullptr, *gms = nullptr;
    const float *w1 = nullptr, *b1 = nullptr, *w2 = nullptr, *b2 = nullptr;
    int n64 = 0;
    for (int i = 0; i < n_in; i++) {
        int sz = in_sizes[i];
        const void* p = d_in[i];
        if (sz == NTOT * CIN)      x  = (const float*)p;
        else if (sz == 2 * NE)     ei = (const int*)p;
        else if (sz == NTOT)       { /* batch: uniform, unused */ }
        else if (sz == CIN) {
            if (n64 == 0) gw = (const float*)p;
            else if (n64 == 1) gb = (const float*)p;
            else gms = (const float*)p;
            n64++;
        }
        else if (sz == CIN * HID)  w1 = (const float*)p;
        else if (sz == HID)        b1 = (const float*)p;
        else if (sz == HID * KC)   w2 = (const float*)p;
        else if (sz == KC)         b2 = (const float*)p;
    }
    float* dout = (float*)d_out;

    statsedgeK<<<128 + NE / 256, 256>>>(x, ei);   // stats blocks || edge blocks
    setupK<<<NTOT / 256, 256>>>(gw, gb, gms);
    aggXK<<<NTOT / 8, 256>>>(x);
    gemmK<<<NTOT / 64, 256>>>(w1, b1);            // f32x2 packed-FMA GEMM
    softmaxK<<<NTOT / 64, 256>>>(w2, b2, dout);
    tracepoolK<<<128 + BG * 16, 256>>>(ei);       // trace blocks || pool blocks
    outlossK<<<BG * KC + 1, 128>>>(dout);
}